// round 13
// baseline (speedup 1.0000x reference)
#include <cuda_runtime.h>
#include <cuda_bf16.h>
#include <math.h>
#include <stdint.h>

// ---------------- problem constants ----------------
constexpr int T_NODES = 50000;
constexpr int NB      = 5000;
constexpr int E_EDGES = 800000;
constexpr int F_IN    = 4652;
constexpr int DIM     = 256;
constexpr int NC      = 5;

// ---------------- scratch ----------------
__device__ float g_t0 [T_NODES * DIM];
__device__ float g_hw [T_NODES * 2 * DIM];
__device__ float g_h1 [T_NODES * DIM];
__device__ float g_h2 [T_NODES * DIM];
__device__ float g_dinv1[T_NODES];
__device__ float g_dinv2[T_NODES];
__device__ float g_r  [NB * 2 * DIM];
__device__ float g_c1 [NB];
__device__ float g_c2 [NB];
__device__ float g_t5 [NB * DIM];
__device__ float g_logits[NB * NC];

// CSR scratch
__device__ int g_cnt1[T_NODES];
__device__ int g_cnt2[T_NODES];
__device__ int g_row1[T_NODES + 1];
__device__ int g_row2[T_NODES + 1];
__device__ int g_csr1[E_EDGES];
__device__ int g_csr2[E_EDGES];
__device__ int g_cur1[T_NODES];
__device__ int g_cur2[T_NODES];
__device__ int g_stmp1[T_NODES];
__device__ int g_stmp2[T_NODES];
__device__ int g_bsum1[256];
__device__ int g_bsum2[256];

// weight-fold scratch (fp32) + folded biases
__device__ __align__(16) float g_wtmp[512 * 256];   // 131072 floats (reused)
__device__ __align__(16) float g_beta1[512];
__device__ __align__(16) float g_beta2[512];
__device__ __align__(16) float g_betaAB[512];       // [0:256]=b_m2b@Wfa_top, [256:512]=bot

// bf16 weight arena: 0=i1, 1=fold1(i2*Wc1), 2=fold2(m1b*Wc2), 3=m1a, 4=m2a, 5=Wx(m2b*fa)
constexpr int NSLOT = 6;
constexpr int SLOT_N[NSLOT] = {256, 512, 512, 256, 256, 256};
constexpr int SLOT_K[NSLOT] = {4672, 256, 256, 512, 512, 512};
constexpr int WB_TOTAL = 2 * (256*4672 + 512*256 + 512*256 + 256*512 + 256*512 + 256*512);
__device__ __align__(16) __nv_bfloat16 g_wb[WB_TOTAL];

// ---------------- helpers ----------------
__device__ __forceinline__ uint32_t smem_u32(const void* p) {
    uint32_t a;
    asm("{ .reg .u64 t; cvta.to.shared.u64 t, %1; cvt.u32.u64 %0, t; }" : "=r"(a) : "l"(p));
    return a;
}
__device__ __forceinline__ uint32_t pack2(__nv_bfloat16 a, __nv_bfloat16 b) {
    return (uint32_t)__bfloat16_as_ushort(a) | ((uint32_t)__bfloat16_as_ushort(b) << 16);
}
__device__ __forceinline__ void ldmx4(uint32_t* r, uint32_t addr) {
    asm volatile("ldmatrix.sync.aligned.m8n8.x4.shared.b16 {%0,%1,%2,%3}, [%4];"
                 : "=r"(r[0]), "=r"(r[1]), "=r"(r[2]), "=r"(r[3]) : "r"(addr));
}
__device__ __forceinline__ void mma16816(float* c, const uint32_t* a, const uint32_t* b) {
    asm volatile("mma.sync.aligned.m16n8k16.row.col.f32.bf16.bf16.f32 "
                 "{%0,%1,%2,%3}, {%4,%5,%6,%7}, {%8,%9}, {%0,%1,%2,%3};"
                 : "+f"(c[0]), "+f"(c[1]), "+f"(c[2]), "+f"(c[3])
                 : "r"(a[0]), "r"(a[1]), "r"(a[2]), "r"(a[3]), "r"(b[0]), "r"(b[1]));
}
__device__ __forceinline__ void cpa16(uint32_t dst, const void* src) {
    asm volatile("cp.async.cg.shared.global [%0], [%1], 16;" :: "r"(dst), "l"(src));
}

// ---------------- weight prep (generalized: source width Nw, col base) --------
__global__ void prep_w_kernel(const float* __restrict__ W, int Nw, int nbase,
                              int Kreal, int Kpad,
                              __nv_bfloat16* __restrict__ bh, __nv_bfloat16* __restrict__ bl) {
    int idx = blockIdx.x * blockDim.x + threadIdx.x;
    if (idx >= 256 * Kpad) return;
    int n = idx / Kpad, k = idx % Kpad;
    float v = (k < Kreal) ? W[(size_t)k * Nw + nbase + n] : 0.f;
    __nv_bfloat16 h = __float2bfloat16(v);
    bh[idx] = h;
    bl[idx] = __float2bfloat16(v - __bfloat162float(h));
}

// bias fold: out[0:256] = b @ Wl, out[256:512] = b @ Wr  (Wl/Wr are [256][256] row-major)
__global__ void fold_bias_kernel(const float* __restrict__ b,
                                 const float* __restrict__ Wl, const float* __restrict__ Wr,
                                 float* __restrict__ out) {
    int n = threadIdx.x;             // 0..511
    const float* W = (n < 256) ? Wl : Wr;
    int nn = n & 255;
    float s = 0.f;
    for (int k = 0; k < 256; k++) s = fmaf(b[k], W[k * 256 + nn], s);
    out[n] = s;
}

// ---------------- pipelined HMMA GEMM, 128x128 tile ----------
constexpr int LDS = 40;
constexpr int TILE_B  = 128 * LDS * 2;
constexpr int STAGE_B = 4 * TILE_B;
constexpr int HM_SMEM = 2 * STAGE_B;

__global__ void __launch_bounds__(256, 2)
hmma_gemm(const float* __restrict__ A, const float* __restrict__ A2, int lda, int splitK,
          const __nv_bfloat16* __restrict__ Bh, const __nv_bfloat16* __restrict__ Bl, int Kpad,
          const float* __restrict__ bias, float* __restrict__ C, int ldc,
          int M, int Kreal, int relu)
{
    extern __shared__ char hsm[];
    const uint32_t sb = smem_u32(hsm);

    const int tid  = threadIdx.x;
    const int wid  = tid >> 5;
    const int lane = tid & 31;
    const int brow = blockIdx.y * 128;
    const int bcol = blockIdx.x * 128;
    const int wm   = (wid & 3) * 32;
    const int wn   = (wid >> 2) * 64;

    float acc[2][8][4];
#pragma unroll
    for (int i = 0; i < 2; i++)
#pragma unroll
        for (int j = 0; j < 8; j++)
#pragma unroll
            for (int q = 0; q < 4; q++) acc[i][j][q] = 0.f;

    const int arow = tid >> 1;
    const int akb  = (tid & 1) * 16;

    const int lg = lane >> 3;
    const int lr = lane & 7;
    const int a_moff = ((lg & 1) ? 8 : 0) + lr;
    const int a_koff = (lg & 2) ? 8 : 0;
    const int b_noff = ((lg & 2) ? 8 : 0) + lr;
    const int b_koff = (lg & 1) ? 8 : 0;

    const int nC = Kpad >> 5;
    float4 av[4];

    auto loadA = [&](int c) {
        const int k0 = c * 32;
        const float* Abase = A; int kb = k0;
        if (A2 && k0 >= splitK) { Abase = A2; kb = k0 - splitK; }
        const int grow = brow + arow;
        const bool rowok = (grow < M);
        const bool fastk = (k0 + 32 <= Kreal);
        const float* src = Abase + (size_t)grow * lda + kb + akb;
#pragma unroll
        for (int i = 0; i < 4; i++) {
            float4 v = make_float4(0.f, 0.f, 0.f, 0.f);
            if (rowok) {
                if (fastk) v = *(const float4*)(src + i * 4);
                else {
                    const int gk = k0 + akb + i * 4;
                    float tmp[4] = {0.f, 0.f, 0.f, 0.f};
                    for (int j = 0; j < 4; j++)
                        if (gk + j < Kreal) tmp[j] = src[i * 4 + j];
                    v = make_float4(tmp[0], tmp[1], tmp[2], tmp[3]);
                }
            }
            av[i] = v;
        }
    };
    auto storeA = [&](uint32_t stg) {
#pragma unroll
        for (int i = 0; i < 4; i++) {
            float4 v = av[i];
            __nv_bfloat16 hx = __float2bfloat16(v.x), hy = __float2bfloat16(v.y);
            __nv_bfloat16 hz = __float2bfloat16(v.z), hw = __float2bfloat16(v.w);
            __nv_bfloat16 lx = __float2bfloat16(v.x - __bfloat162float(hx));
            __nv_bfloat16 ly = __float2bfloat16(v.y - __bfloat162float(hy));
            __nv_bfloat16 lz = __float2bfloat16(v.z - __bfloat162float(hz));
            __nv_bfloat16 lw = __float2bfloat16(v.w - __bfloat162float(hw));
            const uint32_t off = (uint32_t)(arow * LDS + akb + i * 4) * 2;
            asm volatile("st.shared.v2.b32 [%0], {%1,%2};"
                         :: "r"(stg + off), "r"(pack2(hx, hy)), "r"(pack2(hz, hw)));
            asm volatile("st.shared.v2.b32 [%0], {%1,%2};"
                         :: "r"(stg + TILE_B + off), "r"(pack2(lx, ly)), "r"(pack2(lz, lw)));
        }
    };
    auto cpaB = [&](int c, uint32_t stg) {
        const int k0 = c * 32;
        const int nrow = tid >> 1;
        const __nv_bfloat16* sh = Bh + (size_t)(bcol + nrow) * Kpad + k0 + akb;
        const __nv_bfloat16* sl = Bl + (size_t)(bcol + nrow) * Kpad + k0 + akb;
        const uint32_t off0 = (uint32_t)(nrow * LDS + akb) * 2;
#pragma unroll
        for (int j = 0; j < 2; j++) {
            cpa16(stg + 2 * TILE_B + off0 + j * 16, sh + j * 8);
            cpa16(stg + 3 * TILE_B + off0 + j * 16, sl + j * 8);
        }
    };
    auto compute = [&](uint32_t base) {
#pragma unroll
        for (int ks = 0; ks < 2; ks++) {
            const int kk = ks * 16;
            uint32_t ah[2][4], al[2][4];
#pragma unroll
            for (int mt = 0; mt < 2; mt++) {
                const uint32_t aoff =
                    (uint32_t)((wm + mt * 16 + a_moff) * LDS + kk + a_koff) * 2;
                ldmx4(ah[mt], base + aoff);
                ldmx4(al[mt], base + TILE_B + aoff);
            }
#pragma unroll
            for (int p = 0; p < 4; p++) {
                const uint32_t boff =
                    (uint32_t)((wn + p * 16 + b_noff) * LDS + kk + b_koff) * 2;
                uint32_t bhf[4], blf[4];
                ldmx4(bhf, base + 2 * TILE_B + boff);
                ldmx4(blf, base + 3 * TILE_B + boff);
#pragma unroll
                for (int mt = 0; mt < 2; mt++) {
#pragma unroll
                    for (int q = 0; q < 2; q++) {
                        float* c = acc[mt][p * 2 + q];
                        mma16816(c, ah[mt], &bhf[q * 2]);
                        mma16816(c, ah[mt], &blf[q * 2]);
                        mma16816(c, al[mt], &bhf[q * 2]);
                    }
                }
            }
        }
    };

    loadA(0);
    cpaB(0, sb);
    asm volatile("cp.async.commit_group;");
    storeA(sb);
    asm volatile("cp.async.wait_group 0;");
    __syncthreads();

    for (int c = 0; c < nC; c++) {
        const uint32_t cur = sb + (uint32_t)(c & 1) * STAGE_B;
        const uint32_t nxt = sb + (uint32_t)((c + 1) & 1) * STAGE_B;
        const bool more = (c + 1 < nC);
        if (more) {
            loadA(c + 1);
            cpaB(c + 1, nxt);
            asm volatile("cp.async.commit_group;");
        }
        compute(cur);
        if (more) {
            storeA(nxt);
            asm volatile("cp.async.wait_group 0;");
        }
        __syncthreads();
    }

    const int crow0 = brow + wm + (lane >> 2);
    const int ccol0 = bcol + wn + (lane & 3) * 2;
#pragma unroll
    for (int mt = 0; mt < 2; mt++) {
#pragma unroll
        for (int nt = 0; nt < 8; nt++) {
            const int col = ccol0 + nt * 8;
            float bx = 0.f, by = 0.f;
            if (bias) { bx = __ldg(&bias[col]); by = __ldg(&bias[col + 1]); }
            const int r0 = crow0 + mt * 16;
            const int r1 = r0 + 8;
            float v0 = acc[mt][nt][0] + bx, v1 = acc[mt][nt][1] + by;
            float v2 = acc[mt][nt][2] + bx, v3 = acc[mt][nt][3] + by;
            if (relu) {
                v0 = fmaxf(v0, 0.f); v1 = fmaxf(v1, 0.f);
                v2 = fmaxf(v2, 0.f); v3 = fmaxf(v3, 0.f);
            }
            if (r0 < M) *(float2*)(C + (size_t)r0 * ldc + col) = make_float2(v0, v1);
            if (r1 < M) *(float2*)(C + (size_t)r1 * ldc + col) = make_float2(v2, v3);
        }
    }
}

// ---------------- SIMT SGEMM (weight folds + final classifier) ----------------
__global__ __launch_bounds__(256, 2)
void sgemm_kernel(const float* __restrict__ A, int lda,
                  const float* __restrict__ W, const float* __restrict__ bias,
                  float* __restrict__ C, int ldc,
                  int M, int N, int K, int doRelu)
{
    __shared__ float As[16][128];
    __shared__ float Bs[16][128];
    const int t = threadIdx.x;
    const int brow = blockIdx.y * 128;
    const int bcol = blockIdx.x * 128;
    const int tx = t & 15;
    const int ty = t >> 4;
    const bool nvec = ((N & 3) == 0);

    float acc[8][8];
#pragma unroll
    for (int i = 0; i < 8; i++)
#pragma unroll
        for (int j = 0; j < 8; j++) acc[i][j] = 0.f;

    const int ar  = t >> 1;
    const int akv = (t & 1) * 2;

    for (int k0 = 0; k0 < K; k0 += 16) {
#pragma unroll
        for (int i = 0; i < 2; i++) {
            const int kv = akv + i;
            const int gk = k0 + kv * 4;
            const int grow = brow + ar;
            float4 v = make_float4(0.f, 0.f, 0.f, 0.f);
            if (grow < M && gk + 3 < K)
                v = *(const float4*)(A + (size_t)grow * lda + gk);
            else if (grow < M) {
                float tmp[4] = {0.f, 0.f, 0.f, 0.f};
                for (int j = 0; j < 4; j++) if (gk + j < K) tmp[j] = A[(size_t)grow * lda + gk + j];
                v = make_float4(tmp[0], tmp[1], tmp[2], tmp[3]);
            }
            As[kv * 4 + 0][ar] = v.x; As[kv * 4 + 1][ar] = v.y;
            As[kv * 4 + 2][ar] = v.z; As[kv * 4 + 3][ar] = v.w;
        }
#pragma unroll
        for (int i = 0; i < 2; i++) {
            const int idx = t + i * 256;
            const int wr = idx >> 5;
            const int wc = (idx & 31) * 4;
            float4 v = make_float4(0.f, 0.f, 0.f, 0.f);
            const int gk = k0 + wr;
            const int gc = bcol + wc;
            if (gk < K) {
                if (nvec && gc + 3 < N) v = *(const float4*)(W + (size_t)gk * N + gc);
                else {
                    float tmp[4] = {0.f, 0.f, 0.f, 0.f};
                    for (int j = 0; j < 4; j++) if (gc + j < N) tmp[j] = W[(size_t)gk * N + gc + j];
                    v = make_float4(tmp[0], tmp[1], tmp[2], tmp[3]);
                }
            }
            Bs[wr][wc + 0] = v.x; Bs[wr][wc + 1] = v.y;
            Bs[wr][wc + 2] = v.z; Bs[wr][wc + 3] = v.w;
        }
        __syncthreads();
#pragma unroll
        for (int kk = 0; kk < 16; kk++) {
            float a[8], b[8];
#pragma unroll
            for (int i = 0; i < 8; i++) a[i] = As[kk][ty * 8 + i];
#pragma unroll
            for (int j = 0; j < 8; j++) b[j] = Bs[kk][tx * 8 + j];
#pragma unroll
            for (int i = 0; i < 8; i++)
#pragma unroll
                for (int j = 0; j < 8; j++)
                    acc[i][j] = fmaf(a[i], b[j], acc[i][j]);
        }
        __syncthreads();
    }
#pragma unroll
    for (int i = 0; i < 8; i++) {
        const int grow = brow + ty * 8 + i;
        if (grow >= M) continue;
#pragma unroll
        for (int j = 0; j < 8; j++) {
            const int gc = bcol + tx * 8 + j;
            if (gc >= N) continue;
            float v = acc[i][j];
            if (bias) v += bias[gc];
            if (doRelu) v = fmaxf(v, 0.f);
            C[(size_t)grow * ldc + gc] = v;
        }
    }
}

// ---------------- CSR build (batched) ----------------
__global__ void zero4_i_kernel(int* a, int* b, int* c, int* d, int n) {
    int i = blockIdx.x * blockDim.x + threadIdx.x;
    if (i < n) { a[i] = 0; b[i] = 0; c[i] = 0; d[i] = 0; }
}
__global__ void hist2_kernel(const int* __restrict__ ei1, const int* __restrict__ ei2,
                             int* cnt1, int* cnt2, int E) {
    int e = blockIdx.x * blockDim.x + threadIdx.x;
    if (e < E) atomicAdd(&cnt1[ei1[E + e]], 1);
    else if (e < 2 * E) atomicAdd(&cnt2[ei2[E + (e - E)]], 1);
}
__global__ void scan_partial2(const int* __restrict__ in1, const int* __restrict__ in2,
                              int* __restrict__ out1, int* __restrict__ out2,
                              int* __restrict__ bs1, int* __restrict__ bs2, int n) {
    const int* in = blockIdx.y ? in2 : in1;
    int* outp = blockIdx.y ? out2 : out1;
    int* bs = blockIdx.y ? bs2 : bs1;
    __shared__ int s[256];
    int t = threadIdx.x;
    int idx = blockIdx.x * 256 + t;
    s[t] = (idx < n) ? in[idx] : 0;
    __syncthreads();
#pragma unroll
    for (int d = 1; d < 256; d <<= 1) {
        int add = (t >= d) ? s[t - d] : 0;
        __syncthreads();
        s[t] += add;
        __syncthreads();
    }
    if (idx < n) outp[idx] = s[t];
    if (t == 255) bs[blockIdx.x] = s[255];
}
__global__ void scan_block2(int* __restrict__ bs1, int* __restrict__ bs2, int nb) {
    int* bs = blockIdx.y ? bs2 : bs1;
    __shared__ int s[256];
    int t = threadIdx.x;
    s[t] = (t < nb) ? bs[t] : 0;
    __syncthreads();
#pragma unroll
    for (int d = 1; d < 256; d <<= 1) {
        int add = (t >= d) ? s[t - d] : 0;
        __syncthreads();
        s[t] += add;
        __syncthreads();
    }
    if (t < nb) bs[t] = s[t];
}
__global__ void scan_add2(const int* __restrict__ s1, const int* __restrict__ s2,
                          const int* __restrict__ bs1, const int* __restrict__ bs2,
                          int* __restrict__ row1, int* __restrict__ row2, int n) {
    const int* scanned = blockIdx.y ? s2 : s1;
    const int* bs = blockIdx.y ? bs2 : bs1;
    int* row = blockIdx.y ? row2 : row1;
    int idx = blockIdx.x * blockDim.x + threadIdx.x;
    if (idx < n) {
        int b = idx >> 8;
        row[idx + 1] = scanned[idx] + (b > 0 ? bs[b - 1] : 0);
        if (idx == 0) row[0] = 0;
    }
}
__global__ void fill_csr2(const int* __restrict__ ei1, const int* __restrict__ ei2,
                          const int* __restrict__ row1, const int* __restrict__ row2,
                          int* __restrict__ cur1, int* __restrict__ cur2,
                          int* __restrict__ csr1, int* __restrict__ csr2, int E) {
    int e = blockIdx.x * blockDim.x + threadIdx.x;
    if (e < E) {
        int d = ei1[E + e];
        csr1[row1[d] + atomicAdd(&cur1[d], 1)] = ei1[e];
    } else if (e < 2 * E) {
        int e2 = e - E;
        int d = ei2[E + e2];
        csr2[row2[d] + atomicAdd(&cur2[d], 1)] = ei2[e2];
    }
}
__global__ void dinv2_kernel(const int* __restrict__ cnt1, const int* __restrict__ cnt2,
                             float* dinv1, float* dinv2, int n) {
    int i = blockIdx.x * blockDim.x + threadIdx.x;
    if (i < n) dinv1[i] = rsqrtf((float)cnt1[i] + 1.0f);
    else if (i < 2 * n) dinv2[i - n] = rsqrtf((float)cnt2[i - n] + 1.0f);
}

// ---------------- fused GCN aggregate ----
__global__ __launch_bounds__(256, 8)
void gather_conv_kernel(const int* __restrict__ row, const int* __restrict__ csr,
                        const float* __restrict__ dinv, const float* __restrict__ hw, int ldh,
                        const float* __restrict__ bias, float* __restrict__ out, int N) {
    const int d = blockIdx.x * 8 + (threadIdx.x >> 5);
    const int lane = threadIdx.x & 31;
    if (d >= N) return;
    const float dd = dinv[d];

    const float4* self = (const float4*)(hw + (size_t)d * ldh);
    float4 a0 = __ldg(&self[lane]);
    float4 a1 = __ldg(&self[lane + 32]);
    const float sw = dd * dd;
    a0.x *= sw; a0.y *= sw; a0.z *= sw; a0.w *= sw;
    a1.x *= sw; a1.y *= sw; a1.z *= sw; a1.w *= sw;

    const int start = row[d], end = row[d + 1];
#pragma unroll 2
    for (int e = start; e < end; e++) {
        const int s = __ldg(&csr[e]);
        const float nrm = __ldg(&dinv[s]) * dd;
        const float4* hs = (const float4*)(hw + (size_t)s * ldh);
        float4 v0 = __ldg(&hs[lane]);
        float4 v1 = __ldg(&hs[lane + 32]);
        a0.x = fmaf(v0.x, nrm, a0.x); a0.y = fmaf(v0.y, nrm, a0.y);
        a0.z = fmaf(v0.z, nrm, a0.z); a0.w = fmaf(v0.w, nrm, a0.w);
        a1.x = fmaf(v1.x, nrm, a1.x); a1.y = fmaf(v1.y, nrm, a1.y);
        a1.z = fmaf(v1.z, nrm, a1.z); a1.w = fmaf(v1.w, nrm, a1.w);
    }

    const float4 b0 = __ldg(&((const float4*)bias)[lane]);
    const float4 b1 = __ldg(&((const float4*)bias)[lane + 32]);
    a0.x = fmaxf(a0.x + b0.x, 0.f); a0.y = fmaxf(a0.y + b0.y, 0.f);
    a0.z = fmaxf(a0.z + b0.z, 0.f); a0.w = fmaxf(a0.w + b0.w, 0.f);
    a1.x = fmaxf(a1.x + b1.x, 0.f); a1.y = fmaxf(a1.y + b1.y, 0.f);
    a1.z = fmaxf(a1.z + b1.z, 0.f); a1.w = fmaxf(a1.w + b1.w, 0.f);
    float4* orow = (float4*)(out + (size_t)d * DIM);
    orow[lane] = a0;
    orow[lane + 32] = a1;
}

// ---------------- scatter-mean + fixup + softmax ----------------
__device__ __forceinline__ void red4(float* p, float a, float b, float c, float d) {
    asm volatile("red.global.add.v4.f32 [%0], {%1,%2,%3,%4};"
                 :: "l"(p), "f"(a), "f"(b), "f"(c), "f"(d) : "memory");
}
__global__ void zero_rc_kernel(float* r, float* c1, float* c2, int R, int nb) {
    int i = blockIdx.x * blockDim.x + threadIdx.x;
    if (i < R) r[i] = 0.f;
    if (i < nb) { c1[i] = 0.f; c2[i] = 0.f; }
}
__global__ void smean_scatter_kernel(const int* __restrict__ i1, const int* __restrict__ i2,
                                     const float* __restrict__ h, float* __restrict__ r,
                                     float* __restrict__ c1, float* __restrict__ c2, int T) {
    int w = (blockIdx.x * blockDim.x + threadIdx.x) >> 5;
    int lane = threadIdx.x & 31;
    if (w >= T) return;
    int a = i1[w], b = i2[w];
    const float4* hr = (const float4*)(h + (size_t)w * DIM);
    float* ra = r + (size_t)a * (2 * DIM);
    float* rb = r + (size_t)b * (2 * DIM) + DIM;
#pragma unroll
    for (int i = 0; i < 2; i++) {
        float4 v = hr[lane + i * 32];
        red4(ra + (lane + i * 32) * 4, v.x, v.y, v.z, v.w);
        red4(rb + (lane + i * 32) * 4, v.x, v.y, v.z, v.w);
    }
    if (lane == 0) { atomicAdd(&c1[a], 1.f); atomicAdd(&c2[b], 1.f); }
}
__global__ void smean_div_kernel(float* __restrict__ r, const float* __restrict__ c1,
                                 const float* __restrict__ c2, int total) {
    int idx = blockIdx.x * blockDim.x + threadIdx.x;
    if (idx < total) {
        int row = idx >> 9;
        int col = idx & 511;
        float c = (col < DIM) ? c1[row] : c2[row];
        r[idx] = r[idx] / fmaxf(c, 1.f);
    }
}
// add indicator-gated folded biases (b_m2b@Wfa) then relu
__global__ void fixup_relu_kernel(float* __restrict__ t5, const float* __restrict__ c1,
                                  const float* __restrict__ c2,
                                  const float* __restrict__ betaAB, int nb) {
    int idx = blockIdx.x * blockDim.x + threadIdx.x;
    if (idx >= nb * 256) return;
    int i = idx >> 8;
    int n = idx & 255;
    float v = t5[idx];
    if (c1[i] > 0.f) v += betaAB[n];
    if (c2[i] > 0.f) v += betaAB[256 + n];
    t5[idx] = fmaxf(v, 0.f);
}
__global__ void logsoftmax_kernel(const float* __restrict__ logits, float* __restrict__ out, int n) {
    int i = blockIdx.x * blockDim.x + threadIdx.x;
    if (i >= n) return;
    float v[NC];
    float m = -1e30f;
#pragma unroll
    for (int j = 0; j < NC; j++) { v[j] = logits[i * NC + j]; m = fmaxf(m, v[j]); }
    float s = 0.f;
#pragma unroll
    for (int j = 0; j < NC; j++) s += expf(v[j] - m);
    float lse = m + logf(s);
#pragma unroll
    for (int j = 0; j < NC; j++) out[i * NC + j] = v[j] - lse;
}

// ---------------- host launch ----------------
extern "C" void kernel_launch(void* const* d_in, const int* in_sizes, int n_in,
                              void* d_out, int out_size)
{
    const float* x    = (const float*)d_in[0];
    const int*   ei1  = (const int*)d_in[1];
    const int*   ei2  = (const int*)d_in[2];
    const int*   idx1 = (const int*)d_in[3];
    const int*   idx2 = (const int*)d_in[4];
    const float* W_i1 = (const float*)d_in[5];
    const float* b_i1 = (const float*)d_in[6];
    const float* W_i2 = (const float*)d_in[7];
    const float* b_i2 = (const float*)d_in[8];
    const float* Wc11 = (const float*)d_in[9];
    const float* bc11 = (const float*)d_in[10];
    const float* Wc12 = (const float*)d_in[11];
    const float* bc12 = (const float*)d_in[12];
    const float* Wc21 = (const float*)d_in[13];
    const float* bc21 = (const float*)d_in[14];
    const float* Wc22 = (const float*)d_in[15];
    const float* bc22 = (const float*)d_in[16];
    const float* W_m1a = (const float*)d_in[17];
    const float* b_m1a = (const float*)d_in[18];
    const float* W_m1b = (const float*)d_in[19];
    const float* b_m1b = (const float*)d_in[20];
    const float* W_m2a = (const float*)d_in[21];
    const float* b_m2a = (const float*)d_in[22];
    const float* W_m2b = (const float*)d_in[23];
    const float* b_m2b = (const float*)d_in[24];
    const float* W_fa = (const float*)d_in[25];
    const float* b_fa = (const float*)d_in[26];
    const float* W_fb = (const float*)d_in[27];
    const float* b_fb = (const float*)d_in[28];
    float* out = (float*)d_out;

    const int T = T_NODES, E = E_EDGES;

    float *t0, *hw, *h1, *h2, *dinv1, *dinv2, *r, *c1, *c2, *t5, *logits;
    float *wtmp, *beta1, *beta2, *betaAB;
    int *cnt1, *cnt2, *row1, *row2, *csr1, *csr2, *cur1, *cur2, *stmp1, *stmp2, *bsum1, *bsum2;
    __nv_bfloat16* wb;
    cudaGetSymbolAddress((void**)&t0, g_t0);
    cudaGetSymbolAddress((void**)&hw, g_hw);
    cudaGetSymbolAddress((void**)&h1, g_h1);
    cudaGetSymbolAddress((void**)&h2, g_h2);
    cudaGetSymbolAddress((void**)&dinv1, g_dinv1);
    cudaGetSymbolAddress((void**)&dinv2, g_dinv2);
    cudaGetSymbolAddress((void**)&r, g_r);
    cudaGetSymbolAddress((void**)&c1, g_c1);
    cudaGetSymbolAddress((void**)&c2, g_c2);
    cudaGetSymbolAddress((void**)&t5, g_t5);
    cudaGetSymbolAddress((void**)&logits, g_logits);
    cudaGetSymbolAddress((void**)&wb, g_wb);
    cudaGetSymbolAddress((void**)&wtmp, g_wtmp);
    cudaGetSymbolAddress((void**)&beta1, g_beta1);
    cudaGetSymbolAddress((void**)&beta2, g_beta2);
    cudaGetSymbolAddress((void**)&betaAB, g_betaAB);
    cudaGetSymbolAddress((void**)&cnt1, g_cnt1);
    cudaGetSymbolAddress((void**)&cnt2, g_cnt2);
    cudaGetSymbolAddress((void**)&row1, g_row1);
    cudaGetSymbolAddress((void**)&row2, g_row2);
    cudaGetSymbolAddress((void**)&csr1, g_csr1);
    cudaGetSymbolAddress((void**)&csr2, g_csr2);
    cudaGetSymbolAddress((void**)&cur1, g_cur1);
    cudaGetSymbolAddress((void**)&cur2, g_cur2);
    cudaGetSymbolAddress((void**)&stmp1, g_stmp1);
    cudaGetSymbolAddress((void**)&stmp2, g_stmp2);
    cudaGetSymbolAddress((void**)&bsum1, g_bsum1);
    cudaGetSymbolAddress((void**)&bsum2, g_bsum2);

    cudaFuncSetAttribute(hmma_gemm, cudaFuncAttributeMaxDynamicSharedMemorySize, HM_SMEM);

    size_t off[NSLOT];
    {
        size_t o = 0;
        for (int i = 0; i < NSLOT; i++) { off[i] = o; o += 2 * (size_t)SLOT_N[i] * SLOT_K[i]; }
    }
    auto sh_ = [&](int s) { return wb + off[s]; };
    auto sl_ = [&](int s) { return wb + off[s] + (size_t)SLOT_N[s] * SLOT_K[s]; };

    const int threads = 256;
    const dim3 gT(2, (T + 127) / 128);       // N=256 over T rows
    const dim3 gT512(4, (T + 127) / 128);    // N=512 over T rows
    const int blkT = (T + threads - 1) / threads;
    const int blk2E = (2 * E + threads - 1) / threads;
    const int nScanBlk = (T + 255) / 256;
    const int gBlk = (T + 7) / 8;

    // prep of a direct slot (weights already [K][N] with N<=256 stride Nw)
    auto prep = [&](const float* W, int s, int Nw, int nbase, int Kreal) {
        int tot = 256 * SLOT_K[s];
        prep_w_kernel<<<(tot + threads - 1) / threads, threads>>>(
            W, Nw, nbase, Kreal, SLOT_K[s],
            sh_(s) + (size_t)nbase * SLOT_K[s], sl_(s) + (size_t)nbase * SLOT_K[s]);
    };

    // ---- 0,1: direct preps; 2: GEMM1 (ncu window target) ----
    prep(W_i1, 0, 256, 0, F_IN);                                         // 0
    prep(W_m1a, 3, 256, 0, 512);                                         // 1
    hmma_gemm<<<gT, threads, HM_SMEM>>>(x, nullptr, F_IN, 0, sh_(0), sl_(0), 4672,
                                        b_i1, t0, 256, T, F_IN, 1);      // 2 <- profile

    // ---- weight folds (depend only on input weights) ----
    // fold1 = W_i2 @ [Wc11|Wc12]  -> wtmp [256][512]
    sgemm_kernel<<<dim3(2, 2), threads>>>(W_i2, 256, Wc11, nullptr, wtmp, 512, 256, 256, 256, 0);
    sgemm_kernel<<<dim3(2, 2), threads>>>(W_i2, 256, Wc12, nullptr, wtmp + 256, 512, 256, 256, 256, 0);
    fold_bias_kernel<<<1, 512>>>(b_i2, Wc11, Wc12, beta1);
    prep(wtmp, 1, 512, 0, 256);
    prep(wtmp, 1, 512, 256, 256);
    // fold2 = W_m1b @ [Wc21|Wc22]
    sgemm_kernel<<<dim3(2, 2), threads>>>(W_m1b, 256, Wc21, nullptr, wtmp, 512, 256, 256, 256, 0);
    sgemm_kernel<<<dim3(2, 2), threads>>>(W_m1b, 256, Wc22, nullptr, wtmp + 256, 512, 256, 256, 256, 0);
    fold_bias_kernel<<<1, 512>>>(b_m1b, Wc21, Wc22, beta2);
    prep(wtmp, 2, 512, 0, 256);
    prep(wtmp, 2, 512, 256, 256);
    // Wx = [W_m2b@Wfa_top ; W_m2b@Wfa_bot]  -> wtmp [512][256]
    sgemm_kernel<<<dim3(2, 2), threads>>>(W_m2b, 256, W_fa, nullptr, wtmp, 256, 256, 256, 256, 0);
    sgemm_kernel<<<dim3(2, 2), threads>>>(W_m2b, 256, W_fa + 256 * 256, nullptr, wtmp + 256 * 256, 256, 256, 256, 256, 0);
    fold_bias_kernel<<<1, 512>>>(b_m2b, W_fa, W_fa + 256 * 256, betaAB);
    prep(wtmp, 5, 256, 0, 512);
    prep(W_m2a, 4, 256, 0, 512);

    // ---- CSR build + degrees ----
    zero4_i_kernel<<<blkT, threads>>>(cnt1, cnt2, cur1, cur2, T);
    hist2_kernel<<<blk2E, threads>>>(ei1, ei2, cnt1, cnt2, E);
    scan_partial2<<<dim3(nScanBlk, 2), 256>>>(cnt1, cnt2, stmp1, stmp2, bsum1, bsum2, T);
    scan_block2<<<dim3(1, 2), 256>>>(bsum1, bsum2, nScanBlk);
    scan_add2<<<dim3(blkT, 2), threads>>>(stmp1, stmp2, bsum1, bsum2, row1, row2, T);
    fill_csr2<<<blk2E, threads>>>(ei1, ei2, row1, row2, cur1, cur2, csr1, csr2, E);
    dinv2_kernel<<<(2 * T + threads - 1) / threads, threads>>>(cnt1, cnt2, dinv1, dinv2, T);

    // ---- layer 1: fused (i2 ∘ conv-transform) GEMM + gathers + m1a ----
    hmma_gemm<<<gT512, threads, HM_SMEM>>>(t0, nullptr, DIM, 0, sh_(1), sl_(1), 256,
                                           beta1, hw, 512, T, 256, 0);
    gather_conv_kernel<<<gBlk, threads>>>(row1, csr1, dinv1, hw, 512, bc11, h1, T);
    gather_conv_kernel<<<gBlk, threads>>>(row2, csr2, dinv2, hw + 256, 512, bc12, h2, T);
    hmma_gemm<<<gT, threads, HM_SMEM>>>(h1, h2, DIM, 256, sh_(3), sl_(3), 512,
                                        b_m1a, t0, 256, T, 512, 1);

    // ---- layer 2: fused (m1b ∘ conv-transform) + gathers + m2a ----
    hmma_gemm<<<gT512, threads, HM_SMEM>>>(t0, nullptr, DIM, 0, sh_(2), sl_(2), 256,
                                           beta2, hw, 512, T, 256, 0);
    gather_conv_kernel<<<gBlk, threads>>>(row1, csr1, dinv1, hw, 512, bc21, h1, T);
    gather_conv_kernel<<<gBlk, threads>>>(row2, csr2, dinv2, hw + 256, 512, bc22, h2, T);
    hmma_gemm<<<gT, threads, HM_SMEM>>>(h1, h2, DIM, 256, sh_(4), sl_(4), 512,
                                        b_m2a, t0, 256, T, 512, 1);

    // ---- scatter-mean of t0 (m2b folded into Wx) ----
    const int R = NB * 2 * DIM;
    zero_rc_kernel<<<(R + threads - 1) / threads, threads>>>(r, c1, c2, R, NB);
    smean_scatter_kernel<<<(T + 7) / 8, threads>>>(idx1, idx2, t0, r, c1, c2, T);
    smean_div_kernel<<<(R + threads - 1) / threads, threads>>>(r, c1, c2, R);

    // ---- t5 = relu(r @ Wx + b_fa + indicator-biases) ----
    hmma_gemm<<<dim3(2, (NB + 127) / 128), threads, HM_SMEM>>>(r, nullptr, 2 * DIM, 0,
                                        sh_(5), sl_(5), 512, b_fa, t5, 256, NB, 512, 0);
    fixup_relu_kernel<<<(NB * 256 + threads - 1) / threads, threads>>>(t5, c1, c2, betaAB, NB);

    // ---- classifier + log_softmax ----
    sgemm_kernel<<<dim3(1, (NB + 127) / 128), threads>>>(t5, DIM, W_fb, b_fb, logits, NC, NB, NC, DIM, 0);
    logsoftmax_kernel<<<(NB + threads - 1) / threads, threads>>>(logits, out, NB);
}

// round 14
// speedup vs baseline: 1.6627x; 1.6627x over previous
#include <cuda_runtime.h>
#include <cuda_bf16.h>
#include <math.h>
#include <stdint.h>

// ---------------- problem constants ----------------
constexpr int T_NODES = 50000;
constexpr int NB      = 5000;
constexpr int E_EDGES = 800000;
constexpr int F_IN    = 4652;
constexpr int DIM     = 256;
constexpr int NC      = 5;

// ---------------- scratch ----------------
__device__ float g_t0 [T_NODES * DIM];
__device__ float g_hw [T_NODES * 2 * DIM];
__device__ float g_h1 [T_NODES * DIM];
__device__ float g_h2 [T_NODES * DIM];
__device__ float g_dinv1[T_NODES];
__device__ float g_dinv2[T_NODES];
__device__ float g_r  [NB * 2 * DIM];
__device__ float g_c1 [NB];
__device__ float g_c2 [NB];
__device__ float g_t5 [NB * DIM];
__device__ float g_logits[NB * NC];

// CSR scratch
__device__ int g_cnt1[T_NODES];
__device__ int g_cnt2[T_NODES];
__device__ int g_row1[T_NODES + 1];
__device__ int g_row2[T_NODES + 1];
__device__ int g_csr1[E_EDGES];
__device__ int g_csr2[E_EDGES];
__device__ int g_cur1[T_NODES];
__device__ int g_cur2[T_NODES];
__device__ int g_stmp1[T_NODES];
__device__ int g_stmp2[T_NODES];
__device__ int g_bsum1[256];
__device__ int g_bsum2[256];

// weight-fold scratch (fp32) + folded biases
__device__ __align__(16) float g_wtmp[512 * 256];
__device__ __align__(16) float g_beta1[512];
__device__ __align__(16) float g_beta2[512];
__device__ __align__(16) float g_betaAB[512];

// bf16 weight arena: 0=i1, 1=fold1(i2*Wc1), 2=fold2(m1b*Wc2), 3=m1a, 4=m2a, 5=Wx(m2b*fa)
constexpr int NSLOT = 6;
constexpr int SLOT_N[NSLOT] = {256, 512, 512, 256, 256, 256};
constexpr int SLOT_K[NSLOT] = {4672, 256, 256, 512, 512, 512};
constexpr int WB_TOTAL = 2 * (256*4672 + 512*256 + 512*256 + 256*512 + 256*512 + 256*512);
__device__ __align__(16) __nv_bfloat16 g_wb[WB_TOTAL];

// ---------------- helpers ----------------
__device__ __forceinline__ uint32_t smem_u32(const void* p) {
    uint32_t a;
    asm("{ .reg .u64 t; cvta.to.shared.u64 t, %1; cvt.u32.u64 %0, t; }" : "=r"(a) : "l"(p));
    return a;
}
__device__ __forceinline__ uint32_t pack2(__nv_bfloat16 a, __nv_bfloat16 b) {
    return (uint32_t)__bfloat16_as_ushort(a) | ((uint32_t)__bfloat16_as_ushort(b) << 16);
}
__device__ __forceinline__ void ldmx4(uint32_t* r, uint32_t addr) {
    asm volatile("ldmatrix.sync.aligned.m8n8.x4.shared.b16 {%0,%1,%2,%3}, [%4];"
                 : "=r"(r[0]), "=r"(r[1]), "=r"(r[2]), "=r"(r[3]) : "r"(addr));
}
__device__ __forceinline__ void mma16816(float* c, const uint32_t* a, const uint32_t* b) {
    asm volatile("mma.sync.aligned.m16n8k16.row.col.f32.bf16.bf16.f32 "
                 "{%0,%1,%2,%3}, {%4,%5,%6,%7}, {%8,%9}, {%0,%1,%2,%3};"
                 : "+f"(c[0]), "+f"(c[1]), "+f"(c[2]), "+f"(c[3])
                 : "r"(a[0]), "r"(a[1]), "r"(a[2]), "r"(a[3]), "r"(b[0]), "r"(b[1]));
}
__device__ __forceinline__ void cpa16(uint32_t dst, const void* src) {
    asm volatile("cp.async.cg.shared.global [%0], [%1], 16;" :: "r"(dst), "l"(src));
}

// ---------------- weight prep (source width Nw, col base) --------
__global__ void prep_w_kernel(const float* __restrict__ W, int Nw, int nbase,
                              int Kreal, int Kpad,
                              __nv_bfloat16* __restrict__ bh, __nv_bfloat16* __restrict__ bl) {
    int idx = blockIdx.x * blockDim.x + threadIdx.x;
    if (idx >= 256 * Kpad) return;
    int n = idx / Kpad, k = idx % Kpad;
    float v = (k < Kreal) ? W[(size_t)k * Nw + nbase + n] : 0.f;
    __nv_bfloat16 h = __float2bfloat16(v);
    bh[idx] = h;
    bl[idx] = __float2bfloat16(v - __bfloat162float(h));
}

// ---------------- parallel weight folds ----------------
// C[m][n] = sum_k A[m][k] * B[k][n]; one thread per output
__global__ void fold_mat_kernel(const float* __restrict__ A, int lda,
                                const float* __restrict__ B, int ldb,
                                float* __restrict__ C, int ldc,
                                int M, int N, int K) {
    int idx = blockIdx.x * blockDim.x + threadIdx.x;
    if (idx >= M * N) return;
    int m = idx / N, n = idx - m * N;
    const float* a = A + (size_t)m * lda;
    const float* b = B + n;
    float s = 0.f;
#pragma unroll 8
    for (int k = 0; k < K; k++) s = fmaf(__ldg(&a[k]), __ldg(&b[(size_t)k * ldb]), s);
    C[(size_t)m * ldc + n] = s;
}
// out[0:256] = b @ Wl, out[256:512] = b @ Wr; one warp per output
__global__ void fold_bias_kernel(const float* __restrict__ b,
                                 const float* __restrict__ Wl, const float* __restrict__ Wr,
                                 float* __restrict__ out) {
    int n = blockIdx.x;              // 0..511
    int lane = threadIdx.x;          // 0..31
    const float* W = (n < 256) ? Wl : Wr;
    int nn = n & 255;
    float s = 0.f;
    for (int k = lane; k < 256; k += 32)
        s = fmaf(__ldg(&b[k]), __ldg(&W[k * 256 + nn]), s);
#pragma unroll
    for (int o = 16; o; o >>= 1) s += __shfl_xor_sync(0xffffffff, s, o);
    if (lane == 0) out[n] = s;
}

// ---------------- pipelined HMMA GEMM, 128x128 tile ----------
constexpr int LDS = 40;
constexpr int TILE_B  = 128 * LDS * 2;
constexpr int STAGE_B = 4 * TILE_B;
constexpr int HM_SMEM = 2 * STAGE_B;

__global__ void __launch_bounds__(256, 2)
hmma_gemm(const float* __restrict__ A, const float* __restrict__ A2, int lda, int splitK,
          const __nv_bfloat16* __restrict__ Bh, const __nv_bfloat16* __restrict__ Bl, int Kpad,
          const float* __restrict__ bias, float* __restrict__ C, int ldc,
          int M, int Kreal, int relu)
{
    extern __shared__ char hsm[];
    const uint32_t sb = smem_u32(hsm);

    const int tid  = threadIdx.x;
    const int wid  = tid >> 5;
    const int lane = tid & 31;
    const int brow = blockIdx.y * 128;
    const int bcol = blockIdx.x * 128;
    const int wm   = (wid & 3) * 32;
    const int wn   = (wid >> 2) * 64;

    float acc[2][8][4];
#pragma unroll
    for (int i = 0; i < 2; i++)
#pragma unroll
        for (int j = 0; j < 8; j++)
#pragma unroll
            for (int q = 0; q < 4; q++) acc[i][j][q] = 0.f;

    const int arow = tid >> 1;
    const int akb  = (tid & 1) * 16;

    const int lg = lane >> 3;
    const int lr = lane & 7;
    const int a_moff = ((lg & 1) ? 8 : 0) + lr;
    const int a_koff = (lg & 2) ? 8 : 0;
    const int b_noff = ((lg & 2) ? 8 : 0) + lr;
    const int b_koff = (lg & 1) ? 8 : 0;

    const int nC = Kpad >> 5;
    float4 av[4];

    auto loadA = [&](int c) {
        const int k0 = c * 32;
        const float* Abase = A; int kb = k0;
        if (A2 && k0 >= splitK) { Abase = A2; kb = k0 - splitK; }
        const int grow = brow + arow;
        const bool rowok = (grow < M);
        const bool fastk = (k0 + 32 <= Kreal);
        const float* src = Abase + (size_t)grow * lda + kb + akb;
#pragma unroll
        for (int i = 0; i < 4; i++) {
            float4 v = make_float4(0.f, 0.f, 0.f, 0.f);
            if (rowok) {
                if (fastk) v = *(const float4*)(src + i * 4);
                else {
                    const int gk = k0 + akb + i * 4;
                    float tmp[4] = {0.f, 0.f, 0.f, 0.f};
                    for (int j = 0; j < 4; j++)
                        if (gk + j < Kreal) tmp[j] = src[i * 4 + j];
                    v = make_float4(tmp[0], tmp[1], tmp[2], tmp[3]);
                }
            }
            av[i] = v;
        }
    };
    auto storeA = [&](uint32_t stg) {
#pragma unroll
        for (int i = 0; i < 4; i++) {
            float4 v = av[i];
            __nv_bfloat16 hx = __float2bfloat16(v.x), hy = __float2bfloat16(v.y);
            __nv_bfloat16 hz = __float2bfloat16(v.z), hw = __float2bfloat16(v.w);
            __nv_bfloat16 lx = __float2bfloat16(v.x - __bfloat162float(hx));
            __nv_bfloat16 ly = __float2bfloat16(v.y - __bfloat162float(hy));
            __nv_bfloat16 lz = __float2bfloat16(v.z - __bfloat162float(hz));
            __nv_bfloat16 lw = __float2bfloat16(v.w - __bfloat162float(hw));
            const uint32_t off = (uint32_t)(arow * LDS + akb + i * 4) * 2;
            asm volatile("st.shared.v2.b32 [%0], {%1,%2};"
                         :: "r"(stg + off), "r"(pack2(hx, hy)), "r"(pack2(hz, hw)));
            asm volatile("st.shared.v2.b32 [%0], {%1,%2};"
                         :: "r"(stg + TILE_B + off), "r"(pack2(lx, ly)), "r"(pack2(lz, lw)));
        }
    };
    auto cpaB = [&](int c, uint32_t stg) {
        const int k0 = c * 32;
        const int nrow = tid >> 1;
        const __nv_bfloat16* sh = Bh + (size_t)(bcol + nrow) * Kpad + k0 + akb;
        const __nv_bfloat16* sl = Bl + (size_t)(bcol + nrow) * Kpad + k0 + akb;
        const uint32_t off0 = (uint32_t)(nrow * LDS + akb) * 2;
#pragma unroll
        for (int j = 0; j < 2; j++) {
            cpa16(stg + 2 * TILE_B + off0 + j * 16, sh + j * 8);
            cpa16(stg + 3 * TILE_B + off0 + j * 16, sl + j * 8);
        }
    };
    auto compute = [&](uint32_t base) {
#pragma unroll
        for (int ks = 0; ks < 2; ks++) {
            const int kk = ks * 16;
            uint32_t ah[2][4], al[2][4];
#pragma unroll
            for (int mt = 0; mt < 2; mt++) {
                const uint32_t aoff =
                    (uint32_t)((wm + mt * 16 + a_moff) * LDS + kk + a_koff) * 2;
                ldmx4(ah[mt], base + aoff);
                ldmx4(al[mt], base + TILE_B + aoff);
            }
#pragma unroll
            for (int p = 0; p < 4; p++) {
                const uint32_t boff =
                    (uint32_t)((wn + p * 16 + b_noff) * LDS + kk + b_koff) * 2;
                uint32_t bhf[4], blf[4];
                ldmx4(bhf, base + 2 * TILE_B + boff);
                ldmx4(blf, base + 3 * TILE_B + boff);
#pragma unroll
                for (int mt = 0; mt < 2; mt++) {
#pragma unroll
                    for (int q = 0; q < 2; q++) {
                        float* c = acc[mt][p * 2 + q];
                        mma16816(c, ah[mt], &bhf[q * 2]);
                        mma16816(c, ah[mt], &blf[q * 2]);
                        mma16816(c, al[mt], &bhf[q * 2]);
                    }
                }
            }
        }
    };

    loadA(0);
    cpaB(0, sb);
    asm volatile("cp.async.commit_group;");
    storeA(sb);
    asm volatile("cp.async.wait_group 0;");
    __syncthreads();

    for (int c = 0; c < nC; c++) {
        const uint32_t cur = sb + (uint32_t)(c & 1) * STAGE_B;
        const uint32_t nxt = sb + (uint32_t)((c + 1) & 1) * STAGE_B;
        const bool more = (c + 1 < nC);
        if (more) {
            loadA(c + 1);
            cpaB(c + 1, nxt);
            asm volatile("cp.async.commit_group;");
        }
        compute(cur);
        if (more) {
            storeA(nxt);
            asm volatile("cp.async.wait_group 0;");
        }
        __syncthreads();
    }

    const int crow0 = brow + wm + (lane >> 2);
    const int ccol0 = bcol + wn + (lane & 3) * 2;
#pragma unroll
    for (int mt = 0; mt < 2; mt++) {
#pragma unroll
        for (int nt = 0; nt < 8; nt++) {
            const int col = ccol0 + nt * 8;
            float bx = 0.f, by = 0.f;
            if (bias) { bx = __ldg(&bias[col]); by = __ldg(&bias[col + 1]); }
            const int r0 = crow0 + mt * 16;
            const int r1 = r0 + 8;
            float v0 = acc[mt][nt][0] + bx, v1 = acc[mt][nt][1] + by;
            float v2 = acc[mt][nt][2] + bx, v3 = acc[mt][nt][3] + by;
            if (relu) {
                v0 = fmaxf(v0, 0.f); v1 = fmaxf(v1, 0.f);
                v2 = fmaxf(v2, 0.f); v3 = fmaxf(v3, 0.f);
            }
            if (r0 < M) *(float2*)(C + (size_t)r0 * ldc + col) = make_float2(v0, v1);
            if (r1 < M) *(float2*)(C + (size_t)r1 * ldc + col) = make_float2(v2, v3);
        }
    }
}

// ---------------- SIMT SGEMM (final classifier only) ----------------
__global__ __launch_bounds__(256, 2)
void sgemm_kernel(const float* __restrict__ A, int lda,
                  const float* __restrict__ W, const float* __restrict__ bias,
                  float* __restrict__ C, int ldc,
                  int M, int N, int K, int doRelu)
{
    __shared__ float As[16][128];
    __shared__ float Bs[16][128];
    const int t = threadIdx.x;
    const int brow = blockIdx.y * 128;
    const int bcol = blockIdx.x * 128;
    const int tx = t & 15;
    const int ty = t >> 4;
    const bool nvec = ((N & 3) == 0);

    float acc[8][8];
#pragma unroll
    for (int i = 0; i < 8; i++)
#pragma unroll
        for (int j = 0; j < 8; j++) acc[i][j] = 0.f;

    const int ar  = t >> 1;
    const int akv = (t & 1) * 2;

    for (int k0 = 0; k0 < K; k0 += 16) {
#pragma unroll
        for (int i = 0; i < 2; i++) {
            const int kv = akv + i;
            const int gk = k0 + kv * 4;
            const int grow = brow + ar;
            float4 v = make_float4(0.f, 0.f, 0.f, 0.f);
            if (grow < M && gk + 3 < K)
                v = *(const float4*)(A + (size_t)grow * lda + gk);
            else if (grow < M) {
                float tmp[4] = {0.f, 0.f, 0.f, 0.f};
                for (int j = 0; j < 4; j++) if (gk + j < K) tmp[j] = A[(size_t)grow * lda + gk + j];
                v = make_float4(tmp[0], tmp[1], tmp[2], tmp[3]);
            }
            As[kv * 4 + 0][ar] = v.x; As[kv * 4 + 1][ar] = v.y;
            As[kv * 4 + 2][ar] = v.z; As[kv * 4 + 3][ar] = v.w;
        }
#pragma unroll
        for (int i = 0; i < 2; i++) {
            const int idx = t + i * 256;
            const int wr = idx >> 5;
            const int wc = (idx & 31) * 4;
            float4 v = make_float4(0.f, 0.f, 0.f, 0.f);
            const int gk = k0 + wr;
            const int gc = bcol + wc;
            if (gk < K) {
                if (nvec && gc + 3 < N) v = *(const float4*)(W + (size_t)gk * N + gc);
                else {
                    float tmp[4] = {0.f, 0.f, 0.f, 0.f};
                    for (int j = 0; j < 4; j++) if (gc + j < N) tmp[j] = W[(size_t)gk * N + gc + j];
                    v = make_float4(tmp[0], tmp[1], tmp[2], tmp[3]);
                }
            }
            Bs[wr][wc + 0] = v.x; Bs[wr][wc + 1] = v.y;
            Bs[wr][wc + 2] = v.z; Bs[wr][wc + 3] = v.w;
        }
        __syncthreads();
#pragma unroll
        for (int kk = 0; kk < 16; kk++) {
            float a[8], b[8];
#pragma unroll
            for (int i = 0; i < 8; i++) a[i] = As[kk][ty * 8 + i];
#pragma unroll
            for (int j = 0; j < 8; j++) b[j] = Bs[kk][tx * 8 + j];
#pragma unroll
            for (int i = 0; i < 8; i++)
#pragma unroll
                for (int j = 0; j < 8; j++)
                    acc[i][j] = fmaf(a[i], b[j], acc[i][j]);
        }
        __syncthreads();
    }
#pragma unroll
    for (int i = 0; i < 8; i++) {
        const int grow = brow + ty * 8 + i;
        if (grow >= M) continue;
#pragma unroll
        for (int j = 0; j < 8; j++) {
            const int gc = bcol + tx * 8 + j;
            if (gc >= N) continue;
            float v = acc[i][j];
            if (bias) v += bias[gc];
            if (doRelu) v = fmaxf(v, 0.f);
            C[(size_t)grow * ldc + gc] = v;
        }
    }
}

// ---------------- CSR build (batched) ----------------
__global__ void zero4_i_kernel(int* a, int* b, int* c, int* d, int n) {
    int i = blockIdx.x * blockDim.x + threadIdx.x;
    if (i < n) { a[i] = 0; b[i] = 0; c[i] = 0; d[i] = 0; }
}
__global__ void hist2_kernel(const int* __restrict__ ei1, const int* __restrict__ ei2,
                             int* cnt1, int* cnt2, int E) {
    int e = blockIdx.x * blockDim.x + threadIdx.x;
    if (e < E) atomicAdd(&cnt1[ei1[E + e]], 1);
    else if (e < 2 * E) atomicAdd(&cnt2[ei2[E + (e - E)]], 1);
}
__global__ void scan_partial2(const int* __restrict__ in1, const int* __restrict__ in2,
                              int* __restrict__ out1, int* __restrict__ out2,
                              int* __restrict__ bs1, int* __restrict__ bs2, int n) {
    const int* in = blockIdx.y ? in2 : in1;
    int* outp = blockIdx.y ? out2 : out1;
    int* bs = blockIdx.y ? bs2 : bs1;
    __shared__ int s[256];
    int t = threadIdx.x;
    int idx = blockIdx.x * 256 + t;
    s[t] = (idx < n) ? in[idx] : 0;
    __syncthreads();
#pragma unroll
    for (int d = 1; d < 256; d <<= 1) {
        int add = (t >= d) ? s[t - d] : 0;
        __syncthreads();
        s[t] += add;
        __syncthreads();
    }
    if (idx < n) outp[idx] = s[t];
    if (t == 255) bs[blockIdx.x] = s[255];
}
__global__ void scan_block2(int* __restrict__ bs1, int* __restrict__ bs2, int nb) {
    int* bs = blockIdx.y ? bs2 : bs1;
    __shared__ int s[256];
    int t = threadIdx.x;
    s[t] = (t < nb) ? bs[t] : 0;
    __syncthreads();
#pragma unroll
    for (int d = 1; d < 256; d <<= 1) {
        int add = (t >= d) ? s[t - d] : 0;
        __syncthreads();
        s[t] += add;
        __syncthreads();
    }
    if (t < nb) bs[t] = s[t];
}
__global__ void scan_add2(const int* __restrict__ s1, const int* __restrict__ s2,
                          const int* __restrict__ bs1, const int* __restrict__ bs2,
                          int* __restrict__ row1, int* __restrict__ row2, int n) {
    const int* scanned = blockIdx.y ? s2 : s1;
    const int* bs = blockIdx.y ? bs2 : bs1;
    int* row = blockIdx.y ? row2 : row1;
    int idx = blockIdx.x * blockDim.x + threadIdx.x;
    if (idx < n) {
        int b = idx >> 8;
        row[idx + 1] = scanned[idx] + (b > 0 ? bs[b - 1] : 0);
        if (idx == 0) row[0] = 0;
    }
}
__global__ void fill_csr2(const int* __restrict__ ei1, const int* __restrict__ ei2,
                          const int* __restrict__ row1, const int* __restrict__ row2,
                          int* __restrict__ cur1, int* __restrict__ cur2,
                          int* __restrict__ csr1, int* __restrict__ csr2, int E) {
    int e = blockIdx.x * blockDim.x + threadIdx.x;
    if (e < E) {
        int d = ei1[E + e];
        csr1[row1[d] + atomicAdd(&cur1[d], 1)] = ei1[e];
    } else if (e < 2 * E) {
        int e2 = e - E;
        int d = ei2[E + e2];
        csr2[row2[d] + atomicAdd(&cur2[d], 1)] = ei2[e2];
    }
}
__global__ void dinv2_kernel(const int* __restrict__ cnt1, const int* __restrict__ cnt2,
                             float* dinv1, float* dinv2, int n) {
    int i = blockIdx.x * blockDim.x + threadIdx.x;
    if (i < n) dinv1[i] = rsqrtf((float)cnt1[i] + 1.0f);
    else if (i < 2 * n) dinv2[i - n] = rsqrtf((float)cnt2[i - n] + 1.0f);
}

// ---------------- fused GCN aggregate ----
__global__ __launch_bounds__(256, 8)
void gather_conv_kernel(const int* __restrict__ row, const int* __restrict__ csr,
                        const float* __restrict__ dinv, const float* __restrict__ hw, int ldh,
                        const float* __restrict__ bias, float* __restrict__ out, int N) {
    const int d = blockIdx.x * 8 + (threadIdx.x >> 5);
    const int lane = threadIdx.x & 31;
    if (d >= N) return;
    const float dd = dinv[d];

    const float4* self = (const float4*)(hw + (size_t)d * ldh);
    float4 a0 = __ldg(&self[lane]);
    float4 a1 = __ldg(&self[lane + 32]);
    const float sw = dd * dd;
    a0.x *= sw; a0.y *= sw; a0.z *= sw; a0.w *= sw;
    a1.x *= sw; a1.y *= sw; a1.z *= sw; a1.w *= sw;

    const int start = row[d], end = row[d + 1];
#pragma unroll 2
    for (int e = start; e < end; e++) {
        const int s = __ldg(&csr[e]);
        const float nrm = __ldg(&dinv[s]) * dd;
        const float4* hs = (const float4*)(hw + (size_t)s * ldh);
        float4 v0 = __ldg(&hs[lane]);
        float4 v1 = __ldg(&hs[lane + 32]);
        a0.x = fmaf(v0.x, nrm, a0.x); a0.y = fmaf(v0.y, nrm, a0.y);
        a0.z = fmaf(v0.z, nrm, a0.z); a0.w = fmaf(v0.w, nrm, a0.w);
        a1.x = fmaf(v1.x, nrm, a1.x); a1.y = fmaf(v1.y, nrm, a1.y);
        a1.z = fmaf(v1.z, nrm, a1.z); a1.w = fmaf(v1.w, nrm, a1.w);
    }

    const float4 b0 = __ldg(&((const float4*)bias)[lane]);
    const float4 b1 = __ldg(&((const float4*)bias)[lane + 32]);
    a0.x = fmaxf(a0.x + b0.x, 0.f); a0.y = fmaxf(a0.y + b0.y, 0.f);
    a0.z = fmaxf(a0.z + b0.z, 0.f); a0.w = fmaxf(a0.w + b0.w, 0.f);
    a1.x = fmaxf(a1.x + b1.x, 0.f); a1.y = fmaxf(a1.y + b1.y, 0.f);
    a1.z = fmaxf(a1.z + b1.z, 0.f); a1.w = fmaxf(a1.w + b1.w, 0.f);
    float4* orow = (float4*)(out + (size_t)d * DIM);
    orow[lane] = a0;
    orow[lane + 32] = a1;
}

// ---------------- scatter-mean + fixup + softmax ----------------
__device__ __forceinline__ void red4(float* p, float a, float b, float c, float d) {
    asm volatile("red.global.add.v4.f32 [%0], {%1,%2,%3,%4};"
                 :: "l"(p), "f"(a), "f"(b), "f"(c), "f"(d) : "memory");
}
__global__ void zero_rc_kernel(float* r, float* c1, float* c2, int R, int nb) {
    int i = blockIdx.x * blockDim.x + threadIdx.x;
    if (i < R) r[i] = 0.f;
    if (i < nb) { c1[i] = 0.f; c2[i] = 0.f; }
}
__global__ void smean_scatter_kernel(const int* __restrict__ i1, const int* __restrict__ i2,
                                     const float* __restrict__ h, float* __restrict__ r,
                                     float* __restrict__ c1, float* __restrict__ c2, int T) {
    int w = (blockIdx.x * blockDim.x + threadIdx.x) >> 5;
    int lane = threadIdx.x & 31;
    if (w >= T) return;
    int a = i1[w], b = i2[w];
    const float4* hr = (const float4*)(h + (size_t)w * DIM);
    float* ra = r + (size_t)a * (2 * DIM);
    float* rb = r + (size_t)b * (2 * DIM) + DIM;
#pragma unroll
    for (int i = 0; i < 2; i++) {
        float4 v = hr[lane + i * 32];
        red4(ra + (lane + i * 32) * 4, v.x, v.y, v.z, v.w);
        red4(rb + (lane + i * 32) * 4, v.x, v.y, v.z, v.w);
    }
    if (lane == 0) { atomicAdd(&c1[a], 1.f); atomicAdd(&c2[b], 1.f); }
}
__global__ void smean_div_kernel(float* __restrict__ r, const float* __restrict__ c1,
                                 const float* __restrict__ c2, int total) {
    int idx = blockIdx.x * blockDim.x + threadIdx.x;
    if (idx < total) {
        int row = idx >> 9;
        int col = idx & 511;
        float c = (col < DIM) ? c1[row] : c2[row];
        r[idx] = r[idx] / fmaxf(c, 1.f);
    }
}
__global__ void fixup_relu_kernel(float* __restrict__ t5, const float* __restrict__ c1,
                                  const float* __restrict__ c2,
                                  const float* __restrict__ betaAB, int nb) {
    int idx = blockIdx.x * blockDim.x + threadIdx.x;
    if (idx >= nb * 256) return;
    int i = idx >> 8;
    int n = idx & 255;
    float v = t5[idx];
    if (c1[i] > 0.f) v += betaAB[n];
    if (c2[i] > 0.f) v += betaAB[256 + n];
    t5[idx] = fmaxf(v, 0.f);
}
__global__ void logsoftmax_kernel(const float* __restrict__ logits, float* __restrict__ out, int n) {
    int i = blockIdx.x * blockDim.x + threadIdx.x;
    if (i >= n) return;
    float v[NC];
    float m = -1e30f;
#pragma unroll
    for (int j = 0; j < NC; j++) { v[j] = logits[i * NC + j]; m = fmaxf(m, v[j]); }
    float s = 0.f;
#pragma unroll
    for (int j = 0; j < NC; j++) s += expf(v[j] - m);
    float lse = m + logf(s);
#pragma unroll
    for (int j = 0; j < NC; j++) out[i * NC + j] = v[j] - lse;
}

// ---------------- host launch ----------------
extern "C" void kernel_launch(void* const* d_in, const int* in_sizes, int n_in,
                              void* d_out, int out_size)
{
    const float* x    = (const float*)d_in[0];
    const int*   ei1  = (const int*)d_in[1];
    const int*   ei2  = (const int*)d_in[2];
    const int*   idx1 = (const int*)d_in[3];
    const int*   idx2 = (const int*)d_in[4];
    const float* W_i1 = (const float*)d_in[5];
    const float* b_i1 = (const float*)d_in[6];
    const float* W_i2 = (const float*)d_in[7];
    const float* b_i2 = (const float*)d_in[8];
    const float* Wc11 = (const float*)d_in[9];
    const float* bc11 = (const float*)d_in[10];
    const float* Wc12 = (const float*)d_in[11];
    const float* bc12 = (const float*)d_in[12];
    const float* Wc21 = (const float*)d_in[13];
    const float* bc21 = (const float*)d_in[14];
    const float* Wc22 = (const float*)d_in[15];
    const float* bc22 = (const float*)d_in[16];
    const float* W_m1a = (const float*)d_in[17];
    const float* b_m1a = (const float*)d_in[18];
    const float* W_m1b = (const float*)d_in[19];
    const float* b_m1b = (const float*)d_in[20];
    const float* W_m2a = (const float*)d_in[21];
    const float* b_m2a = (const float*)d_in[22];
    const float* W_m2b = (const float*)d_in[23];
    const float* b_m2b = (const float*)d_in[24];
    const float* W_fa = (const float*)d_in[25];
    const float* b_fa = (const float*)d_in[26];
    const float* W_fb = (const float*)d_in[27];
    const float* b_fb = (const float*)d_in[28];
    float* out = (float*)d_out;

    const int T = T_NODES, E = E_EDGES;

    float *t0, *hw, *h1, *h2, *dinv1, *dinv2, *r, *c1, *c2, *t5, *logits;
    float *wtmp, *beta1, *beta2, *betaAB;
    int *cnt1, *cnt2, *row1, *row2, *csr1, *csr2, *cur1, *cur2, *stmp1, *stmp2, *bsum1, *bsum2;
    __nv_bfloat16* wb;
    cudaGetSymbolAddress((void**)&t0, g_t0);
    cudaGetSymbolAddress((void**)&hw, g_hw);
    cudaGetSymbolAddress((void**)&h1, g_h1);
    cudaGetSymbolAddress((void**)&h2, g_h2);
    cudaGetSymbolAddress((void**)&dinv1, g_dinv1);
    cudaGetSymbolAddress((void**)&dinv2, g_dinv2);
    cudaGetSymbolAddress((void**)&r, g_r);
    cudaGetSymbolAddress((void**)&c1, g_c1);
    cudaGetSymbolAddress((void**)&c2, g_c2);
    cudaGetSymbolAddress((void**)&t5, g_t5);
    cudaGetSymbolAddress((void**)&logits, g_logits);
    cudaGetSymbolAddress((void**)&wb, g_wb);
    cudaGetSymbolAddress((void**)&wtmp, g_wtmp);
    cudaGetSymbolAddress((void**)&beta1, g_beta1);
    cudaGetSymbolAddress((void**)&beta2, g_beta2);
    cudaGetSymbolAddress((void**)&betaAB, g_betaAB);
    cudaGetSymbolAddress((void**)&cnt1, g_cnt1);
    cudaGetSymbolAddress((void**)&cnt2, g_cnt2);
    cudaGetSymbolAddress((void**)&row1, g_row1);
    cudaGetSymbolAddress((void**)&row2, g_row2);
    cudaGetSymbolAddress((void**)&csr1, g_csr1);
    cudaGetSymbolAddress((void**)&csr2, g_csr2);
    cudaGetSymbolAddress((void**)&cur1, g_cur1);
    cudaGetSymbolAddress((void**)&cur2, g_cur2);
    cudaGetSymbolAddress((void**)&stmp1, g_stmp1);
    cudaGetSymbolAddress((void**)&stmp2, g_stmp2);
    cudaGetSymbolAddress((void**)&bsum1, g_bsum1);
    cudaGetSymbolAddress((void**)&bsum2, g_bsum2);

    cudaFuncSetAttribute(hmma_gemm, cudaFuncAttributeMaxDynamicSharedMemorySize, HM_SMEM);

    size_t off[NSLOT];
    {
        size_t o = 0;
        for (int i = 0; i < NSLOT; i++) { off[i] = o; o += 2 * (size_t)SLOT_N[i] * SLOT_K[i]; }
    }
    auto sh_ = [&](int s) { return wb + off[s]; };
    auto sl_ = [&](int s) { return wb + off[s] + (size_t)SLOT_N[s] * SLOT_K[s]; };

    const int threads = 256;
    const dim3 gT(2, (T + 127) / 128);
    const dim3 gT512(4, (T + 127) / 128);
    const int blkT = (T + threads - 1) / threads;
    const int blk2E = (2 * E + threads - 1) / threads;
    const int nScanBlk = (T + 255) / 256;
    const int gBlk = (T + 7) / 8;

    auto prep = [&](const float* W, int s, int Nw, int nbase, int Kreal) {
        int tot = 256 * SLOT_K[s];
        prep_w_kernel<<<(tot + threads - 1) / threads, threads>>>(
            W, Nw, nbase, Kreal, SLOT_K[s],
            sh_(s) + (size_t)nbase * SLOT_K[s], sl_(s) + (size_t)nbase * SLOT_K[s]);
    };
    auto fold = [&](const float* A, int lda, const float* B, int ldb,
                    float* C, int ldc, int M, int N, int K) {
        fold_mat_kernel<<<(M * N + threads - 1) / threads, threads>>>(A, lda, B, ldb, C, ldc, M, N, K);
    };

    // ---- 0,1: direct preps; 2: GEMM1 (ncu window target) ----
    prep(W_i1, 0, 256, 0, F_IN);                                         // 0
    prep(W_m1a, 3, 256, 0, 512);                                         // 1
    hmma_gemm<<<gT, threads, HM_SMEM>>>(x, nullptr, F_IN, 0, sh_(0), sl_(0), 4672,
                                        b_i1, t0, 256, T, F_IN, 1);      // 2 <- profile

    // ---- weight folds (parallel flat kernels) ----
    // fold1 = W_i2 @ [Wc11|Wc12]  -> wtmp [256][512]
    fold(W_i2, 256, Wc11, 256, wtmp, 512, 256, 256, 256);
    fold(W_i2, 256, Wc12, 256, wtmp + 256, 512, 256, 256, 256);
    fold_bias_kernel<<<512, 32>>>(b_i2, Wc11, Wc12, beta1);
    prep(wtmp, 1, 512, 0, 256);
    prep(wtmp, 1, 512, 256, 256);
    // fold2 = W_m1b @ [Wc21|Wc22]
    fold(W_m1b, 256, Wc21, 256, wtmp, 512, 256, 256, 256);
    fold(W_m1b, 256, Wc22, 256, wtmp + 256, 512, 256, 256, 256);
    fold_bias_kernel<<<512, 32>>>(b_m1b, Wc21, Wc22, beta2);
    prep(wtmp, 2, 512, 0, 256);
    prep(wtmp, 2, 512, 256, 256);
    // Wx = [W_m2b@Wfa_top ; W_m2b@Wfa_bot] -> wtmp [512][256]
    fold(W_m2b, 256, W_fa, 256, wtmp, 256, 256, 256, 256);
    fold(W_m2b, 256, W_fa + 256 * 256, 256, wtmp + 256 * 256, 256, 256, 256, 256);
    fold_bias_kernel<<<512, 32>>>(b_m2b, W_fa, W_fa + 256 * 256, betaAB);
    prep(wtmp, 5, 256, 0, 512);
    prep(W_m2a, 4, 256, 0, 512);

    // ---- CSR build + degrees ----
    zero4_i_kernel<<<blkT, threads>>>(cnt1, cnt2, cur1, cur2, T);
    hist2_kernel<<<blk2E, threads>>>(ei1, ei2, cnt1, cnt2, E);
    scan_partial2<<<dim3(nScanBlk, 2), 256>>>(cnt1, cnt2, stmp1, stmp2, bsum1, bsum2, T);
    scan_block2<<<dim3(1, 2), 256>>>(bsum1, bsum2, nScanBlk);
    scan_add2<<<dim3(blkT, 2), threads>>>(stmp1, stmp2, bsum1, bsum2, row1, row2, T);
    fill_csr2<<<blk2E, threads>>>(ei1, ei2, row1, row2, cur1, cur2, csr1, csr2, E);
    dinv2_kernel<<<(2 * T + threads - 1) / threads, threads>>>(cnt1, cnt2, dinv1, dinv2, T);

    // ---- layer 1: fused (i2 ∘ conv-transform) GEMM + gathers + m1a ----
    hmma_gemm<<<gT512, threads, HM_SMEM>>>(t0, nullptr, DIM, 0, sh_(1), sl_(1), 256,
                                           beta1, hw, 512, T, 256, 0);
    gather_conv_kernel<<<gBlk, threads>>>(row1, csr1, dinv1, hw, 512, bc11, h1, T);
    gather_conv_kernel<<<gBlk, threads>>>(row2, csr2, dinv2, hw + 256, 512, bc12, h2, T);
    hmma_gemm<<<gT, threads, HM_SMEM>>>(h1, h2, DIM, 256, sh_(3), sl_(3), 512,
                                        b_m1a, t0, 256, T, 512, 1);

    // ---- layer 2: fused (m1b ∘ conv-transform) + gathers + m2a ----
    hmma_gemm<<<gT512, threads, HM_SMEM>>>(t0, nullptr, DIM, 0, sh_(2), sl_(2), 256,
                                           beta2, hw, 512, T, 256, 0);
    gather_conv_kernel<<<gBlk, threads>>>(row1, csr1, dinv1, hw, 512, bc21, h1, T);
    gather_conv_kernel<<<gBlk, threads>>>(row2, csr2, dinv2, hw + 256, 512, bc22, h2, T);
    hmma_gemm<<<gT, threads, HM_SMEM>>>(h1, h2, DIM, 256, sh_(4), sl_(4), 512,
                                        b_m2a, t0, 256, T, 512, 1);

    // ---- scatter-mean of t0 (m2b folded into Wx) ----
    const int R = NB * 2 * DIM;
    zero_rc_kernel<<<(R + threads - 1) / threads, threads>>>(r, c1, c2, R, NB);
    smean_scatter_kernel<<<(T + 7) / 8, threads>>>(idx1, idx2, t0, r, c1, c2, T);
    smean_div_kernel<<<(R + threads - 1) / threads, threads>>>(r, c1, c2, R);

    // ---- t5 = relu(r @ Wx + b_fa + indicator-biases) ----
    hmma_gemm<<<dim3(2, (NB + 127) / 128), threads, HM_SMEM>>>(r, nullptr, 2 * DIM, 0,
                                        sh_(5), sl_(5), 512, b_fa, t5, 256, NB, 512, 0);
    fixup_relu_kernel<<<(NB * 256 + threads - 1) / threads, threads>>>(t5, c1, c2, betaAB, NB);

    // ---- classifier + log_softmax ----
    sgemm_kernel<<<dim3(1, (NB + 127) / 128), threads>>>(t5, DIM, W_fb, b_fb, logits, NC, NB, NC, DIM, 0);
    logsoftmax_kernel<<<(NB + threads - 1) / threads, threads>>>(logits, out, NB);
}

// round 15
// speedup vs baseline: 1.7820x; 1.0717x over previous
#include <cuda_runtime.h>
#include <cuda_bf16.h>
#include <math.h>
#include <stdint.h>

// ---------------- problem constants ----------------
constexpr int T_NODES = 50000;
constexpr int NB      = 5000;
constexpr int E_EDGES = 800000;
constexpr int F_IN    = 4652;
constexpr int DIM     = 256;
constexpr int NC      = 5;

// ---------------- scratch ----------------
__device__ float g_t0 [T_NODES * DIM];
__device__ float g_hw [T_NODES * 2 * DIM];
__device__ float g_h1 [T_NODES * DIM];
__device__ float g_h2 [T_NODES * DIM];
__device__ float g_dinv1[T_NODES];
__device__ float g_dinv2[T_NODES];
__device__ float g_r  [NB * 2 * DIM];
__device__ float g_c1 [NB];
__device__ float g_c2 [NB];
__device__ float g_t5 [NB * DIM];
__device__ float g_logits[NB * NC];

// CSR scratch
__device__ int g_cnt1[T_NODES];
__device__ int g_cnt2[T_NODES];
__device__ int g_row1[T_NODES + 1];
__device__ int g_row2[T_NODES + 1];
__device__ int g_csr1[E_EDGES];
__device__ int g_csr2[E_EDGES];
__device__ int g_cur1[T_NODES];
__device__ int g_cur2[T_NODES];
__device__ int g_stmp1[T_NODES];
__device__ int g_stmp2[T_NODES];
__device__ int g_bsum1[256];
__device__ int g_bsum2[256];

// weight-fold scratch (3 disjoint buffers) + folded biases
__device__ __align__(16) float g_wtmp1[256 * 512];   // fold1 [256k][512n]
__device__ __align__(16) float g_wtmp2[256 * 512];   // fold2 [256k][512n]
__device__ __align__(16) float g_wtmp3[512 * 256];   // Wx    [512k][256n]
__device__ __align__(16) float g_beta1[512];
__device__ __align__(16) float g_beta2[512];
__device__ __align__(16) float g_betaAB[512];

// bf16 weight arena: 0=i1, 1=fold1, 2=fold2, 3=m1a, 4=m2a, 5=Wx
constexpr int NSLOT = 6;
constexpr int SLOT_N[NSLOT] = {256, 512, 512, 256, 256, 256};
constexpr int SLOT_K[NSLOT] = {4672, 256, 256, 512, 512, 512};
constexpr int WB_TOTAL = 2 * (256*4672 + 512*256 + 512*256 + 256*512 + 256*512 + 256*512);
__device__ __align__(16) __nv_bfloat16 g_wb[WB_TOTAL];

// ---------------- helpers ----------------
__device__ __forceinline__ uint32_t smem_u32(const void* p) {
    uint32_t a;
    asm("{ .reg .u64 t; cvta.to.shared.u64 t, %1; cvt.u32.u64 %0, t; }" : "=r"(a) : "l"(p));
    return a;
}
__device__ __forceinline__ uint32_t pack2(__nv_bfloat16 a, __nv_bfloat16 b) {
    return (uint32_t)__bfloat16_as_ushort(a) | ((uint32_t)__bfloat16_as_ushort(b) << 16);
}
__device__ __forceinline__ void ldmx4(uint32_t* r, uint32_t addr) {
    asm volatile("ldmatrix.sync.aligned.m8n8.x4.shared.b16 {%0,%1,%2,%3}, [%4];"
                 : "=r"(r[0]), "=r"(r[1]), "=r"(r[2]), "=r"(r[3]) : "r"(addr));
}
__device__ __forceinline__ void mma16816(float* c, const uint32_t* a, const uint32_t* b) {
    asm volatile("mma.sync.aligned.m16n8k16.row.col.f32.bf16.bf16.f32 "
                 "{%0,%1,%2,%3}, {%4,%5,%6,%7}, {%8,%9}, {%0,%1,%2,%3};"
                 : "+f"(c[0]), "+f"(c[1]), "+f"(c[2]), "+f"(c[3])
                 : "r"(a[0]), "r"(a[1]), "r"(a[2]), "r"(a[3]), "r"(b[0]), "r"(b[1]));
}
__device__ __forceinline__ void cpa16(uint32_t dst, const void* src) {
    asm volatile("cp.async.cg.shared.global [%0], [%1], 16;" :: "r"(dst), "l"(src));
}

// ---------------- weight prep (Nrows generalized) --------
__global__ void prep_w_kernel(const float* __restrict__ W, int Nw, int Nrows,
                              int Kreal, int Kpad,
                              __nv_bfloat16* __restrict__ bh, __nv_bfloat16* __restrict__ bl) {
    int idx = blockIdx.x * blockDim.x + threadIdx.x;
    if (idx >= Nrows * Kpad) return;
    int n = idx / Kpad, k = idx % Kpad;
    float v = (k < Kreal) ? W[(size_t)k * Nw + n] : 0.f;
    __nv_bfloat16 h = __float2bfloat16(v);
    bh[idx] = h;
    bl[idx] = __float2bfloat16(v - __bfloat162float(h));
}

// ---------------- batched weight folds (all 6 in one launch) ----------------
__global__ void fold_all_kernel(const float* __restrict__ Wi2,
                                const float* __restrict__ Wc11, const float* __restrict__ Wc12,
                                const float* __restrict__ Wm1b,
                                const float* __restrict__ Wc21, const float* __restrict__ Wc22,
                                const float* __restrict__ Wm2b, const float* __restrict__ Wfa,
                                float* __restrict__ w1, float* __restrict__ w2,
                                float* __restrict__ w3) {
    const int op = blockIdx.y;
    const int idx = blockIdx.x * blockDim.x + threadIdx.x;   // 0..65535
    const float *A, *B;
    float* C;
    int ldc;
    switch (op) {
        case 0: A = Wi2;  B = Wc11;              C = w1;               ldc = 512; break;
        case 1: A = Wi2;  B = Wc12;              C = w1 + 256;         ldc = 512; break;
        case 2: A = Wm1b; B = Wc21;              C = w2;               ldc = 512; break;
        case 3: A = Wm1b; B = Wc22;              C = w2 + 256;         ldc = 512; break;
        case 4: A = Wm2b; B = Wfa;               C = w3;               ldc = 256; break;
        default:A = Wm2b; B = Wfa + 256 * 256;   C = w3 + 256 * 256;   ldc = 256; break;
    }
    const int m = idx >> 8;
    const int n = idx & 255;
    const float* a = A + (size_t)m * 256;
    const float* b = B + n;
    float s = 0.f;
#pragma unroll 8
    for (int k = 0; k < 256; k++) s = fmaf(__ldg(&a[k]), __ldg(&b[(size_t)k * 256]), s);
    C[(size_t)m * ldc + n] = s;
}
// all 3 bias folds in one launch: grid (512, 3), block 32
__global__ void fold_bias3_kernel(const float* __restrict__ bi2,
                                  const float* __restrict__ Wc11, const float* __restrict__ Wc12,
                                  const float* __restrict__ bm1b,
                                  const float* __restrict__ Wc21, const float* __restrict__ Wc22,
                                  const float* __restrict__ bm2b, const float* __restrict__ Wfa,
                                  float* __restrict__ beta1, float* __restrict__ beta2,
                                  float* __restrict__ betaAB) {
    const int op = blockIdx.y;
    const int n = blockIdx.x;
    const int lane = threadIdx.x;
    const float *b, *Wl, *Wr;
    float* out;
    if (op == 0)      { b = bi2;  Wl = Wc11; Wr = Wc12;            out = beta1; }
    else if (op == 1) { b = bm1b; Wl = Wc21; Wr = Wc22;            out = beta2; }
    else              { b = bm2b; Wl = Wfa;  Wr = Wfa + 256 * 256; out = betaAB; }
    const float* W = (n < 256) ? Wl : Wr;
    const int nn = n & 255;
    float s = 0.f;
    for (int k = lane; k < 256; k += 32)
        s = fmaf(__ldg(&b[k]), __ldg(&W[k * 256 + nn]), s);
#pragma unroll
    for (int o = 16; o; o >>= 1) s += __shfl_xor_sync(0xffffffff, s, o);
    if (lane == 0) out[n] = s;
}

// ---------------- pipelined HMMA GEMM, 128x128 tile ----------
constexpr int LDS = 40;
constexpr int TILE_B  = 128 * LDS * 2;
constexpr int STAGE_B = 4 * TILE_B;
constexpr int HM_SMEM = 2 * STAGE_B;

__global__ void __launch_bounds__(256, 2)
hmma_gemm(const float* __restrict__ A, const float* __restrict__ A2, int lda, int splitK,
          const __nv_bfloat16* __restrict__ Bh, const __nv_bfloat16* __restrict__ Bl, int Kpad,
          const float* __restrict__ bias, float* __restrict__ C, int ldc,
          int M, int Kreal, int relu)
{
    extern __shared__ char hsm[];
    const uint32_t sb = smem_u32(hsm);

    const int tid  = threadIdx.x;
    const int wid  = tid >> 5;
    const int lane = tid & 31;
    const int brow = blockIdx.y * 128;
    const int bcol = blockIdx.x * 128;
    const int wm   = (wid & 3) * 32;
    const int wn   = (wid >> 2) * 64;

    float acc[2][8][4];
#pragma unroll
    for (int i = 0; i < 2; i++)
#pragma unroll
        for (int j = 0; j < 8; j++)
#pragma unroll
            for (int q = 0; q < 4; q++) acc[i][j][q] = 0.f;

    const int arow = tid >> 1;
    const int akb  = (tid & 1) * 16;

    const int lg = lane >> 3;
    const int lr = lane & 7;
    const int a_moff = ((lg & 1) ? 8 : 0) + lr;
    const int a_koff = (lg & 2) ? 8 : 0;
    const int b_noff = ((lg & 2) ? 8 : 0) + lr;
    const int b_koff = (lg & 1) ? 8 : 0;

    const int nC = Kpad >> 5;
    float4 av[4];

    auto loadA = [&](int c) {
        const int k0 = c * 32;
        const float* Abase = A; int kb = k0;
        if (A2 && k0 >= splitK) { Abase = A2; kb = k0 - splitK; }
        const int grow = brow + arow;
        const bool rowok = (grow < M);
        const bool fastk = (k0 + 32 <= Kreal);
        const float* src = Abase + (size_t)grow * lda + kb + akb;
#pragma unroll
        for (int i = 0; i < 4; i++) {
            float4 v = make_float4(0.f, 0.f, 0.f, 0.f);
            if (rowok) {
                if (fastk) v = *(const float4*)(src + i * 4);
                else {
                    const int gk = k0 + akb + i * 4;
                    float tmp[4] = {0.f, 0.f, 0.f, 0.f};
                    for (int j = 0; j < 4; j++)
                        if (gk + j < Kreal) tmp[j] = src[i * 4 + j];
                    v = make_float4(tmp[0], tmp[1], tmp[2], tmp[3]);
                }
            }
            av[i] = v;
        }
    };
    auto storeA = [&](uint32_t stg) {
#pragma unroll
        for (int i = 0; i < 4; i++) {
            float4 v = av[i];
            __nv_bfloat16 hx = __float2bfloat16(v.x), hy = __float2bfloat16(v.y);
            __nv_bfloat16 hz = __float2bfloat16(v.z), hw = __float2bfloat16(v.w);
            __nv_bfloat16 lx = __float2bfloat16(v.x - __bfloat162float(hx));
            __nv_bfloat16 ly = __float2bfloat16(v.y - __bfloat162float(hy));
            __nv_bfloat16 lz = __float2bfloat16(v.z - __bfloat162float(hz));
            __nv_bfloat16 lw = __float2bfloat16(v.w - __bfloat162float(hw));
            const uint32_t off = (uint32_t)(arow * LDS + akb + i * 4) * 2;
            asm volatile("st.shared.v2.b32 [%0], {%1,%2};"
                         :: "r"(stg + off), "r"(pack2(hx, hy)), "r"(pack2(hz, hw)));
            asm volatile("st.shared.v2.b32 [%0], {%1,%2};"
                         :: "r"(stg + TILE_B + off), "r"(pack2(lx, ly)), "r"(pack2(lz, lw)));
        }
    };
    auto cpaB = [&](int c, uint32_t stg) {
        const int k0 = c * 32;
        const int nrow = tid >> 1;
        const __nv_bfloat16* sh = Bh + (size_t)(bcol + nrow) * Kpad + k0 + akb;
        const __nv_bfloat16* sl = Bl + (size_t)(bcol + nrow) * Kpad + k0 + akb;
        const uint32_t off0 = (uint32_t)(nrow * LDS + akb) * 2;
#pragma unroll
        for (int j = 0; j < 2; j++) {
            cpa16(stg + 2 * TILE_B + off0 + j * 16, sh + j * 8);
            cpa16(stg + 3 * TILE_B + off0 + j * 16, sl + j * 8);
        }
    };
    auto compute = [&](uint32_t base) {
#pragma unroll
        for (int ks = 0; ks < 2; ks++) {
            const int kk = ks * 16;
            uint32_t ah[2][4], al[2][4];
#pragma unroll
            for (int mt = 0; mt < 2; mt++) {
                const uint32_t aoff =
                    (uint32_t)((wm + mt * 16 + a_moff) * LDS + kk + a_koff) * 2;
                ldmx4(ah[mt], base + aoff);
                ldmx4(al[mt], base + TILE_B + aoff);
            }
#pragma unroll
            for (int p = 0; p < 4; p++) {
                const uint32_t boff =
                    (uint32_t)((wn + p * 16 + b_noff) * LDS + kk + b_koff) * 2;
                uint32_t bhf[4], blf[4];
                ldmx4(bhf, base + 2 * TILE_B + boff);
                ldmx4(blf, base + 3 * TILE_B + boff);
#pragma unroll
                for (int mt = 0; mt < 2; mt++) {
#pragma unroll
                    for (int q = 0; q < 2; q++) {
                        float* c = acc[mt][p * 2 + q];
                        mma16816(c, ah[mt], &bhf[q * 2]);
                        mma16816(c, ah[mt], &blf[q * 2]);
                        mma16816(c, al[mt], &bhf[q * 2]);
                    }
                }
            }
        }
    };

    loadA(0);
    cpaB(0, sb);
    asm volatile("cp.async.commit_group;");
    storeA(sb);
    asm volatile("cp.async.wait_group 0;");
    __syncthreads();

    for (int c = 0; c < nC; c++) {
        const uint32_t cur = sb + (uint32_t)(c & 1) * STAGE_B;
        const uint32_t nxt = sb + (uint32_t)((c + 1) & 1) * STAGE_B;
        const bool more = (c + 1 < nC);
        if (more) {
            loadA(c + 1);
            cpaB(c + 1, nxt);
            asm volatile("cp.async.commit_group;");
        }
        compute(cur);
        if (more) {
            storeA(nxt);
            asm volatile("cp.async.wait_group 0;");
        }
        __syncthreads();
    }

    const int crow0 = brow + wm + (lane >> 2);
    const int ccol0 = bcol + wn + (lane & 3) * 2;
#pragma unroll
    for (int mt = 0; mt < 2; mt++) {
#pragma unroll
        for (int nt = 0; nt < 8; nt++) {
            const int col = ccol0 + nt * 8;
            float bx = 0.f, by = 0.f;
            if (bias) { bx = __ldg(&bias[col]); by = __ldg(&bias[col + 1]); }
            const int r0 = crow0 + mt * 16;
            const int r1 = r0 + 8;
            float v0 = acc[mt][nt][0] + bx, v1 = acc[mt][nt][1] + by;
            float v2 = acc[mt][nt][2] + bx, v3 = acc[mt][nt][3] + by;
            if (relu) {
                v0 = fmaxf(v0, 0.f); v1 = fmaxf(v1, 0.f);
                v2 = fmaxf(v2, 0.f); v3 = fmaxf(v3, 0.f);
            }
            if (r0 < M) *(float2*)(C + (size_t)r0 * ldc + col) = make_float2(v0, v1);
            if (r1 < M) *(float2*)(C + (size_t)r1 * ldc + col) = make_float2(v2, v3);
        }
    }
}

// ---------------- SIMT SGEMM (final classifier) ----------------
__global__ __launch_bounds__(256, 2)
void sgemm_kernel(const float* __restrict__ A, int lda,
                  const float* __restrict__ W, const float* __restrict__ bias,
                  float* __restrict__ C, int ldc,
                  int M, int N, int K, int doRelu)
{
    __shared__ float As[16][128];
    __shared__ float Bs[16][128];
    const int t = threadIdx.x;
    const int brow = blockIdx.y * 128;
    const int bcol = blockIdx.x * 128;
    const int tx = t & 15;
    const int ty = t >> 4;
    const bool nvec = ((N & 3) == 0);

    float acc[8][8];
#pragma unroll
    for (int i = 0; i < 8; i++)
#pragma unroll
        for (int j = 0; j < 8; j++) acc[i][j] = 0.f;

    const int ar  = t >> 1;
    const int akv = (t & 1) * 2;

    for (int k0 = 0; k0 < K; k0 += 16) {
#pragma unroll
        for (int i = 0; i < 2; i++) {
            const int kv = akv + i;
            const int gk = k0 + kv * 4;
            const int grow = brow + ar;
            float4 v = make_float4(0.f, 0.f, 0.f, 0.f);
            if (grow < M && gk + 3 < K)
                v = *(const float4*)(A + (size_t)grow * lda + gk);
            else if (grow < M) {
                float tmp[4] = {0.f, 0.f, 0.f, 0.f};
                for (int j = 0; j < 4; j++) if (gk + j < K) tmp[j] = A[(size_t)grow * lda + gk + j];
                v = make_float4(tmp[0], tmp[1], tmp[2], tmp[3]);
            }
            As[kv * 4 + 0][ar] = v.x; As[kv * 4 + 1][ar] = v.y;
            As[kv * 4 + 2][ar] = v.z; As[kv * 4 + 3][ar] = v.w;
        }
#pragma unroll
        for (int i = 0; i < 2; i++) {
            const int idx = t + i * 256;
            const int wr = idx >> 5;
            const int wc = (idx & 31) * 4;
            float4 v = make_float4(0.f, 0.f, 0.f, 0.f);
            const int gk = k0 + wr;
            const int gc = bcol + wc;
            if (gk < K) {
                if (nvec && gc + 3 < N) v = *(const float4*)(W + (size_t)gk * N + gc);
                else {
                    float tmp[4] = {0.f, 0.f, 0.f, 0.f};
                    for (int j = 0; j < 4; j++) if (gc + j < N) tmp[j] = W[(size_t)gk * N + gc + j];
                    v = make_float4(tmp[0], tmp[1], tmp[2], tmp[3]);
                }
            }
            Bs[wr][wc + 0] = v.x; Bs[wr][wc + 1] = v.y;
            Bs[wr][wc + 2] = v.z; Bs[wr][wc + 3] = v.w;
        }
        __syncthreads();
#pragma unroll
        for (int kk = 0; kk < 16; kk++) {
            float a[8], b[8];
#pragma unroll
            for (int i = 0; i < 8; i++) a[i] = As[kk][ty * 8 + i];
#pragma unroll
            for (int j = 0; j < 8; j++) b[j] = Bs[kk][tx * 8 + j];
#pragma unroll
            for (int i = 0; i < 8; i++)
#pragma unroll
                for (int j = 0; j < 8; j++)
                    acc[i][j] = fmaf(a[i], b[j], acc[i][j]);
        }
        __syncthreads();
    }
#pragma unroll
    for (int i = 0; i < 8; i++) {
        const int grow = brow + ty * 8 + i;
        if (grow >= M) continue;
#pragma unroll
        for (int j = 0; j < 8; j++) {
            const int gc = bcol + tx * 8 + j;
            if (gc >= N) continue;
            float v = acc[i][j];
            if (bias) v += bias[gc];
            if (doRelu) v = fmaxf(v, 0.f);
            C[(size_t)grow * ldc + gc] = v;
        }
    }
}

// ---------------- CSR build (batched) ----------------
__global__ void zero4_i_kernel(int* a, int* b, int* c, int* d, int n) {
    int i = blockIdx.x * blockDim.x + threadIdx.x;
    if (i < n) { a[i] = 0; b[i] = 0; c[i] = 0; d[i] = 0; }
}
__global__ void hist2_kernel(const int* __restrict__ ei1, const int* __restrict__ ei2,
                             int* cnt1, int* cnt2, int E) {
    int e = blockIdx.x * blockDim.x + threadIdx.x;
    if (e < E) atomicAdd(&cnt1[ei1[E + e]], 1);
    else if (e < 2 * E) atomicAdd(&cnt2[ei2[E + (e - E)]], 1);
}
__global__ void scan_partial2(const int* __restrict__ in1, const int* __restrict__ in2,
                              int* __restrict__ out1, int* __restrict__ out2,
                              int* __restrict__ bs1, int* __restrict__ bs2, int n) {
    const int* in = blockIdx.y ? in2 : in1;
    int* outp = blockIdx.y ? out2 : out1;
    int* bs = blockIdx.y ? bs2 : bs1;
    __shared__ int s[256];
    int t = threadIdx.x;
    int idx = blockIdx.x * 256 + t;
    s[t] = (idx < n) ? in[idx] : 0;
    __syncthreads();
#pragma unroll
    for (int d = 1; d < 256; d <<= 1) {
        int add = (t >= d) ? s[t - d] : 0;
        __syncthreads();
        s[t] += add;
        __syncthreads();
    }
    if (idx < n) outp[idx] = s[t];
    if (t == 255) bs[blockIdx.x] = s[255];
}
__global__ void scan_block2(int* __restrict__ bs1, int* __restrict__ bs2, int nb) {
    int* bs = blockIdx.y ? bs2 : bs1;
    __shared__ int s[256];
    int t = threadIdx.x;
    s[t] = (t < nb) ? bs[t] : 0;
    __syncthreads();
#pragma unroll
    for (int d = 1; d < 256; d <<= 1) {
        int add = (t >= d) ? s[t - d] : 0;
        __syncthreads();
        s[t] += add;
        __syncthreads();
    }
    if (t < nb) bs[t] = s[t];
}
__global__ void scan_add2(const int* __restrict__ s1, const int* __restrict__ s2,
                          const int* __restrict__ bs1, const int* __restrict__ bs2,
                          int* __restrict__ row1, int* __restrict__ row2, int n) {
    const int* scanned = blockIdx.y ? s2 : s1;
    const int* bs = blockIdx.y ? bs2 : bs1;
    int* row = blockIdx.y ? row2 : row1;
    int idx = blockIdx.x * blockDim.x + threadIdx.x;
    if (idx < n) {
        int b = idx >> 8;
        row[idx + 1] = scanned[idx] + (b > 0 ? bs[b - 1] : 0);
        if (idx == 0) row[0] = 0;
    }
}
__global__ void fill_csr2(const int* __restrict__ ei1, const int* __restrict__ ei2,
                          const int* __restrict__ row1, const int* __restrict__ row2,
                          int* __restrict__ cur1, int* __restrict__ cur2,
                          int* __restrict__ csr1, int* __restrict__ csr2, int E) {
    int e = blockIdx.x * blockDim.x + threadIdx.x;
    if (e < E) {
        int d = ei1[E + e];
        csr1[row1[d] + atomicAdd(&cur1[d], 1)] = ei1[e];
    } else if (e < 2 * E) {
        int e2 = e - E;
        int d = ei2[E + e2];
        csr2[row2[d] + atomicAdd(&cur2[d], 1)] = ei2[e2];
    }
}
__global__ void dinv2_kernel(const int* __restrict__ cnt1, const int* __restrict__ cnt2,
                             float* dinv1, float* dinv2, int n) {
    int i = blockIdx.x * blockDim.x + threadIdx.x;
    if (i < n) dinv1[i] = rsqrtf((float)cnt1[i] + 1.0f);
    else if (i < 2 * n) dinv2[i - n] = rsqrtf((float)cnt2[i - n] + 1.0f);
}

// ---------------- fused GCN aggregate ----
__global__ __launch_bounds__(256, 8)
void gather_conv_kernel(const int* __restrict__ row, const int* __restrict__ csr,
                        const float* __restrict__ dinv, const float* __restrict__ hw, int ldh,
                        const float* __restrict__ bias, float* __restrict__ out, int N) {
    const int d = blockIdx.x * 8 + (threadIdx.x >> 5);
    const int lane = threadIdx.x & 31;
    if (d >= N) return;
    const float dd = dinv[d];

    const float4* self = (const float4*)(hw + (size_t)d * ldh);
    float4 a0 = __ldg(&self[lane]);
    float4 a1 = __ldg(&self[lane + 32]);
    const float sw = dd * dd;
    a0.x *= sw; a0.y *= sw; a0.z *= sw; a0.w *= sw;
    a1.x *= sw; a1.y *= sw; a1.z *= sw; a1.w *= sw;

    const int start = row[d], end = row[d + 1];
#pragma unroll 2
    for (int e = start; e < end; e++) {
        const int s = __ldg(&csr[e]);
        const float nrm = __ldg(&dinv[s]) * dd;
        const float4* hs = (const float4*)(hw + (size_t)s * ldh);
        float4 v0 = __ldg(&hs[lane]);
        float4 v1 = __ldg(&hs[lane + 32]);
        a0.x = fmaf(v0.x, nrm, a0.x); a0.y = fmaf(v0.y, nrm, a0.y);
        a0.z = fmaf(v0.z, nrm, a0.z); a0.w = fmaf(v0.w, nrm, a0.w);
        a1.x = fmaf(v1.x, nrm, a1.x); a1.y = fmaf(v1.y, nrm, a1.y);
        a1.z = fmaf(v1.z, nrm, a1.z); a1.w = fmaf(v1.w, nrm, a1.w);
    }

    const float4 b0 = __ldg(&((const float4*)bias)[lane]);
    const float4 b1 = __ldg(&((const float4*)bias)[lane + 32]);
    a0.x = fmaxf(a0.x + b0.x, 0.f); a0.y = fmaxf(a0.y + b0.y, 0.f);
    a0.z = fmaxf(a0.z + b0.z, 0.f); a0.w = fmaxf(a0.w + b0.w, 0.f);
    a1.x = fmaxf(a1.x + b1.x, 0.f); a1.y = fmaxf(a1.y + b1.y, 0.f);
    a1.z = fmaxf(a1.z + b1.z, 0.f); a1.w = fmaxf(a1.w + b1.w, 0.f);
    float4* orow = (float4*)(out + (size_t)d * DIM);
    orow[lane] = a0;
    orow[lane + 32] = a1;
}

// ---------------- scatter-mean + fixup + softmax ----------------
__device__ __forceinline__ void red4(float* p, float a, float b, float c, float d) {
    asm volatile("red.global.add.v4.f32 [%0], {%1,%2,%3,%4};"
                 :: "l"(p), "f"(a), "f"(b), "f"(c), "f"(d) : "memory");
}
__global__ void zero_rc_kernel(float* r, float* c1, float* c2, int R, int nb) {
    int i = blockIdx.x * blockDim.x + threadIdx.x;
    if (i < R) r[i] = 0.f;
    if (i < nb) { c1[i] = 0.f; c2[i] = 0.f; }
}
__global__ void smean_scatter_kernel(const int* __restrict__ i1, const int* __restrict__ i2,
                                     const float* __restrict__ h, float* __restrict__ r,
                                     float* __restrict__ c1, float* __restrict__ c2, int T) {
    int w = (blockIdx.x * blockDim.x + threadIdx.x) >> 5;
    int lane = threadIdx.x & 31;
    if (w >= T) return;
    int a = i1[w], b = i2[w];
    const float4* hr = (const float4*)(h + (size_t)w * DIM);
    float* ra = r + (size_t)a * (2 * DIM);
    float* rb = r + (size_t)b * (2 * DIM) + DIM;
#pragma unroll
    for (int i = 0; i < 2; i++) {
        float4 v = hr[lane + i * 32];
        red4(ra + (lane + i * 32) * 4, v.x, v.y, v.z, v.w);
        red4(rb + (lane + i * 32) * 4, v.x, v.y, v.z, v.w);
    }
    if (lane == 0) { atomicAdd(&c1[a], 1.f); atomicAdd(&c2[b], 1.f); }
}
__global__ void smean_div_kernel(float* __restrict__ r, const float* __restrict__ c1,
                                 const float* __restrict__ c2, int total) {
    int idx = blockIdx.x * blockDim.x + threadIdx.x;
    if (idx < total) {
        int row = idx >> 9;
        int col = idx & 511;
        float c = (col < DIM) ? c1[row] : c2[row];
        r[idx] = r[idx] / fmaxf(c, 1.f);
    }
}
__global__ void fixup_relu_kernel(float* __restrict__ t5, const float* __restrict__ c1,
                                  const float* __restrict__ c2,
                                  const float* __restrict__ betaAB, int nb) {
    int idx = blockIdx.x * blockDim.x + threadIdx.x;
    if (idx >= nb * 256) return;
    int i = idx >> 8;
    int n = idx & 255;
    float v = t5[idx];
    if (c1[i] > 0.f) v += betaAB[n];
    if (c2[i] > 0.f) v += betaAB[256 + n];
    t5[idx] = fmaxf(v, 0.f);
}
__global__ void logsoftmax_kernel(const float* __restrict__ logits, float* __restrict__ out, int n) {
    int i = blockIdx.x * blockDim.x + threadIdx.x;
    if (i >= n) return;
    float v[NC];
    float m = -1e30f;
#pragma unroll
    for (int j = 0; j < NC; j++) { v[j] = logits[i * NC + j]; m = fmaxf(m, v[j]); }
    float s = 0.f;
#pragma unroll
    for (int j = 0; j < NC; j++) s += expf(v[j] - m);
    float lse = m + logf(s);
#pragma unroll
    for (int j = 0; j < NC; j++) out[i * NC + j] = v[j] - lse;
}

// ---------------- host launch ----------------
extern "C" void kernel_launch(void* const* d_in, const int* in_sizes, int n_in,
                              void* d_out, int out_size)
{
    const float* x    = (const float*)d_in[0];
    const int*   ei1  = (const int*)d_in[1];
    const int*   ei2  = (const int*)d_in[2];
    const int*   idx1 = (const int*)d_in[3];
    const int*   idx2 = (const int*)d_in[4];
    const float* W_i1 = (const float*)d_in[5];
    const float* b_i1 = (const float*)d_in[6];
    const float* W_i2 = (const float*)d_in[7];
    const float* b_i2 = (const float*)d_in[8];
    const float* Wc11 = (const float*)d_in[9];
    const float* bc11 = (const float*)d_in[10];
    const float* Wc12 = (const float*)d_in[11];
    const float* bc12 = (const float*)d_in[12];
    const float* Wc21 = (const float*)d_in[13];
    const float* bc21 = (const float*)d_in[14];
    const float* Wc22 = (const float*)d_in[15];
    const float* bc22 = (const float*)d_in[16];
    const float* W_m1a = (const float*)d_in[17];
    const float* b_m1a = (const float*)d_in[18];
    const float* W_m1b = (const float*)d_in[19];
    const float* b_m1b = (const float*)d_in[20];
    const float* W_m2a = (const float*)d_in[21];
    const float* b_m2a = (const float*)d_in[22];
    const float* W_m2b = (const float*)d_in[23];
    const float* b_m2b = (const float*)d_in[24];
    const float* W_fa = (const float*)d_in[25];
    const float* b_fa = (const float*)d_in[26];
    const float* W_fb = (const float*)d_in[27];
    const float* b_fb = (const float*)d_in[28];
    float* out = (float*)d_out;

    const int T = T_NODES, E = E_EDGES;

    float *t0, *hw, *h1, *h2, *dinv1, *dinv2, *r, *c1, *c2, *t5, *logits;
    float *wtmp1, *wtmp2, *wtmp3, *beta1, *beta2, *betaAB;
    int *cnt1, *cnt2, *row1, *row2, *csr1, *csr2, *cur1, *cur2, *stmp1, *stmp2, *bsum1, *bsum2;
    __nv_bfloat16* wb;
    cudaGetSymbolAddress((void**)&t0, g_t0);
    cudaGetSymbolAddress((void**)&hw, g_hw);
    cudaGetSymbolAddress((void**)&h1, g_h1);
    cudaGetSymbolAddress((void**)&h2, g_h2);
    cudaGetSymbolAddress((void**)&dinv1, g_dinv1);
    cudaGetSymbolAddress((void**)&dinv2, g_dinv2);
    cudaGetSymbolAddress((void**)&r, g_r);
    cudaGetSymbolAddress((void**)&c1, g_c1);
    cudaGetSymbolAddress((void**)&c2, g_c2);
    cudaGetSymbolAddress((void**)&t5, g_t5);
    cudaGetSymbolAddress((void**)&logits, g_logits);
    cudaGetSymbolAddress((void**)&wb, g_wb);
    cudaGetSymbolAddress((void**)&wtmp1, g_wtmp1);
    cudaGetSymbolAddress((void**)&wtmp2, g_wtmp2);
    cudaGetSymbolAddress((void**)&wtmp3, g_wtmp3);
    cudaGetSymbolAddress((void**)&beta1, g_beta1);
    cudaGetSymbolAddress((void**)&beta2, g_beta2);
    cudaGetSymbolAddress((void**)&betaAB, g_betaAB);
    cudaGetSymbolAddress((void**)&cnt1, g_cnt1);
    cudaGetSymbolAddress((void**)&cnt2, g_cnt2);
    cudaGetSymbolAddress((void**)&row1, g_row1);
    cudaGetSymbolAddress((void**)&row2, g_row2);
    cudaGetSymbolAddress((void**)&csr1, g_csr1);
    cudaGetSymbolAddress((void**)&csr2, g_csr2);
    cudaGetSymbolAddress((void**)&cur1, g_cur1);
    cudaGetSymbolAddress((void**)&cur2, g_cur2);
    cudaGetSymbolAddress((void**)&stmp1, g_stmp1);
    cudaGetSymbolAddress((void**)&stmp2, g_stmp2);
    cudaGetSymbolAddress((void**)&bsum1, g_bsum1);
    cudaGetSymbolAddress((void**)&bsum2, g_bsum2);

    cudaFuncSetAttribute(hmma_gemm, cudaFuncAttributeMaxDynamicSharedMemorySize, HM_SMEM);

    size_t off[NSLOT];
    {
        size_t o = 0;
        for (int i = 0; i < NSLOT; i++) { off[i] = o; o += 2 * (size_t)SLOT_N[i] * SLOT_K[i]; }
    }
    auto sh_ = [&](int s) { return wb + off[s]; };
    auto sl_ = [&](int s) { return wb + off[s] + (size_t)SLOT_N[s] * SLOT_K[s]; };

    const int threads = 256;
    const dim3 gT(2, (T + 127) / 128);
    const dim3 gT512(4, (T + 127) / 128);
    const int blkT = (T + threads - 1) / threads;
    const int blk2E = (2 * E + threads - 1) / threads;
    const int nScanBlk = (T + 255) / 256;
    const int gBlk = (T + 7) / 8;

    auto prep = [&](const float* W, int s, int Nw, int Kreal) {
        int tot = SLOT_N[s] * SLOT_K[s];
        prep_w_kernel<<<(tot + threads - 1) / threads, threads>>>(
            W, Nw, SLOT_N[s], Kreal, SLOT_K[s], sh_(s), sl_(s));
    };

    // ---- 0: prep i1; 1: fold_all; 2: GEMM1 (profile target) ----
    prep(W_i1, 0, 256, F_IN);                                            // 0
    fold_all_kernel<<<dim3(256, 6), threads>>>(W_i2, Wc11, Wc12,
                                               W_m1b, Wc21, Wc22,
                                               W_m2b, W_fa,
                                               wtmp1, wtmp2, wtmp3);     // 1
    hmma_gemm<<<gT, threads, HM_SMEM>>>(x, nullptr, F_IN, 0, sh_(0), sl_(0), 4672,
                                        b_i1, t0, 256, T, F_IN, 1);      // 2 <- profile

    // ---- remaining preps + bias folds (batched) ----
    fold_bias3_kernel<<<dim3(512, 3), 32>>>(b_i2, Wc11, Wc12, b_m1b, Wc21, Wc22,
                                            b_m2b, W_fa, beta1, beta2, betaAB);
    prep(wtmp1, 1, 512, 256);
    prep(wtmp2, 2, 512, 256);
    prep(W_m1a, 3, 256, 512);
    prep(W_m2a, 4, 256, 512);
    prep(wtmp3, 5, 256, 512);

    // ---- CSR build + degrees ----
    zero4_i_kernel<<<blkT, threads>>>(cnt1, cnt2, cur1, cur2, T);
    hist2_kernel<<<blk2E, threads>>>(ei1, ei2, cnt1, cnt2, E);
    scan_partial2<<<dim3(nScanBlk, 2), 256>>>(cnt1, cnt2, stmp1, stmp2, bsum1, bsum2, T);
    scan_block2<<<dim3(1, 2), 256>>>(bsum1, bsum2, nScanBlk);
    scan_add2<<<dim3(blkT, 2), threads>>>(stmp1, stmp2, bsum1, bsum2, row1, row2, T);
    fill_csr2<<<blk2E, threads>>>(ei1, ei2, row1, row2, cur1, cur2, csr1, csr2, E);
    dinv2_kernel<<<(2 * T + threads - 1) / threads, threads>>>(cnt1, cnt2, dinv1, dinv2, T);

    // ---- layer 1 ----
    hmma_gemm<<<gT512, threads, HM_SMEM>>>(t0, nullptr, DIM, 0, sh_(1), sl_(1), 256,
                                           beta1, hw, 512, T, 256, 0);
    gather_conv_kernel<<<gBlk, threads>>>(row1, csr1, dinv1, hw, 512, bc11, h1, T);
    gather_conv_kernel<<<gBlk, threads>>>(row2, csr2, dinv2, hw + 256, 512, bc12, h2, T);
    hmma_gemm<<<gT, threads, HM_SMEM>>>(h1, h2, DIM, 256, sh_(3), sl_(3), 512,
                                        b_m1a, t0, 256, T, 512, 1);

    // ---- layer 2 ----
    hmma_gemm<<<gT512, threads, HM_SMEM>>>(t0, nullptr, DIM, 0, sh_(2), sl_(2), 256,
                                           beta2, hw, 512, T, 256, 0);
    gather_conv_kernel<<<gBlk, threads>>>(row1, csr1, dinv1, hw, 512, bc21, h1, T);
    gather_conv_kernel<<<gBlk, threads>>>(row2, csr2, dinv2, hw + 256, 512, bc22, h2, T);
    hmma_gemm<<<gT, threads, HM_SMEM>>>(h1, h2, DIM, 256, sh_(4), sl_(4), 512,
                                        b_m2a, t0, 256, T, 512, 1);

    // ---- scatter-mean of t0 ----
    const int R = NB * 2 * DIM;
    zero_rc_kernel<<<(R + threads - 1) / threads, threads>>>(r, c1, c2, R, NB);
    smean_scatter_kernel<<<(T + 7) / 8, threads>>>(idx1, idx2, t0, r, c1, c2, T);
    smean_div_kernel<<<(R + threads - 1) / threads, threads>>>(r, c1, c2, R);

    // ---- t5 = relu(r @ Wx + b_fa + indicator-biases) ----
    hmma_gemm<<<dim3(2, (NB + 127) / 128), threads, HM_SMEM>>>(r, nullptr, 2 * DIM, 0,
                                        sh_(5), sl_(5), 512, b_fa, t5, 256, NB, 512, 0);
    fixup_relu_kernel<<<(NB * 256 + threads - 1) / threads, threads>>>(t5, c1, c2, betaAB, NB);

    // ---- classifier + log_softmax ----
    sgemm_kernel<<<dim3(1, (NB + 127) / 128), threads>>>(t5, DIM, W_fb, b_fb, logits, NC, NB, NC, DIM, 0);
    logsoftmax_kernel<<<(NB + threads - 1) / threads, threads>>>(logits, out, NB);
}

// round 16
// speedup vs baseline: 1.8421x; 1.0338x over previous
#include <cuda_runtime.h>
#include <cuda_bf16.h>
#include <math.h>
#include <stdint.h>

// ---------------- problem constants ----------------
constexpr int T_NODES = 50000;
constexpr int NB      = 5000;
constexpr int E_EDGES = 800000;
constexpr int F_IN    = 4652;
constexpr int DIM     = 256;
constexpr int NC      = 5;

// ---------------- aux stream (created at program load, pre-checkpoint) -------
struct AuxStreams {
    cudaStream_t s2 = nullptr;
    cudaEvent_t evF = nullptr, evJ = nullptr;
    AuxStreams() {
        cudaStreamCreateWithFlags(&s2, cudaStreamNonBlocking);
        cudaEventCreateWithFlags(&evF, cudaEventDisableTiming);
        cudaEventCreateWithFlags(&evJ, cudaEventDisableTiming);
    }
};
static AuxStreams g_aux;

// ---------------- scratch ----------------
__device__ float g_t0 [T_NODES * DIM];
__device__ float g_hw [T_NODES * 2 * DIM];
__device__ float g_h1 [T_NODES * DIM];
__device__ float g_h2 [T_NODES * DIM];
__device__ float g_dinv1[T_NODES];
__device__ float g_dinv2[T_NODES];
__device__ float g_r  [NB * 2 * DIM];
__device__ float g_c1 [NB];
__device__ float g_c2 [NB];
__device__ float g_t5 [NB * DIM];
__device__ float g_logits[NB * NC];

// CSR scratch
__device__ int g_cnt1[T_NODES];
__device__ int g_cnt2[T_NODES];
__device__ int g_row1[T_NODES + 1];
__device__ int g_row2[T_NODES + 1];
__device__ int g_csr1[E_EDGES];
__device__ int g_csr2[E_EDGES];
__device__ int g_cur1[T_NODES];
__device__ int g_cur2[T_NODES];
__device__ int g_stmp1[T_NODES];
__device__ int g_stmp2[T_NODES];
__device__ int g_bsum1[256];
__device__ int g_bsum2[256];

// weight-fold scratch + folded biases
__device__ __align__(16) float g_wtmp1[256 * 512];
__device__ __align__(16) float g_wtmp2[256 * 512];
__device__ __align__(16) float g_wtmp3[512 * 256];
__device__ __align__(16) float g_beta1[512];
__device__ __align__(16) float g_beta2[512];
__device__ __align__(16) float g_betaAB[512];

// bf16 weight arena: 0=i1, 1=fold1, 2=fold2, 3=m1a, 4=m2a, 5=Wx
constexpr int NSLOT = 6;
constexpr int SLOT_N[NSLOT] = {256, 512, 512, 256, 256, 256};
constexpr int SLOT_K[NSLOT] = {4672, 256, 256, 512, 512, 512};
constexpr int WB_TOTAL = 2 * (256*4672 + 512*256 + 512*256 + 256*512 + 256*512 + 256*512);
__device__ __align__(16) __nv_bfloat16 g_wb[WB_TOTAL];

// ---------------- helpers ----------------
__device__ __forceinline__ uint32_t smem_u32(const void* p) {
    uint32_t a;
    asm("{ .reg .u64 t; cvta.to.shared.u64 t, %1; cvt.u32.u64 %0, t; }" : "=r"(a) : "l"(p));
    return a;
}
__device__ __forceinline__ uint32_t pack2(__nv_bfloat16 a, __nv_bfloat16 b) {
    return (uint32_t)__bfloat16_as_ushort(a) | ((uint32_t)__bfloat16_as_ushort(b) << 16);
}
__device__ __forceinline__ void ldmx4(uint32_t* r, uint32_t addr) {
    asm volatile("ldmatrix.sync.aligned.m8n8.x4.shared.b16 {%0,%1,%2,%3}, [%4];"
                 : "=r"(r[0]), "=r"(r[1]), "=r"(r[2]), "=r"(r[3]) : "r"(addr));
}
__device__ __forceinline__ void mma16816(float* c, const uint32_t* a, const uint32_t* b) {
    asm volatile("mma.sync.aligned.m16n8k16.row.col.f32.bf16.bf16.f32 "
                 "{%0,%1,%2,%3}, {%4,%5,%6,%7}, {%8,%9}, {%0,%1,%2,%3};"
                 : "+f"(c[0]), "+f"(c[1]), "+f"(c[2]), "+f"(c[3])
                 : "r"(a[0]), "r"(a[1]), "r"(a[2]), "r"(a[3]), "r"(b[0]), "r"(b[1]));
}
__device__ __forceinline__ void cpa16(uint32_t dst, const void* src) {
    asm volatile("cp.async.cg.shared.global [%0], [%1], 16;" :: "r"(dst), "l"(src));
}

// ---------------- weight prep ----------------
__global__ void prep_w_kernel(const float* __restrict__ W, int Nw, int Nrows,
                              int Kreal, int Kpad,
                              __nv_bfloat16* __restrict__ bh, __nv_bfloat16* __restrict__ bl) {
    int idx = blockIdx.x * blockDim.x + threadIdx.x;
    if (idx >= Nrows * Kpad) return;
    int n = idx / Kpad, k = idx % Kpad;
    float v = (k < Kreal) ? W[(size_t)k * Nw + n] : 0.f;
    __nv_bfloat16 h = __float2bfloat16(v);
    bh[idx] = h;
    bl[idx] = __float2bfloat16(v - __bfloat162float(h));
}

// ---------------- batched weight folds ----------------
__global__ void fold_all_kernel(const float* __restrict__ Wi2,
                                const float* __restrict__ Wc11, const float* __restrict__ Wc12,
                                const float* __restrict__ Wm1b,
                                const float* __restrict__ Wc21, const float* __restrict__ Wc22,
                                const float* __restrict__ Wm2b, const float* __restrict__ Wfa,
                                float* __restrict__ w1, float* __restrict__ w2,
                                float* __restrict__ w3) {
    const int op = blockIdx.y;
    const int idx = blockIdx.x * blockDim.x + threadIdx.x;
    const float *A, *B;
    float* C;
    int ldc;
    switch (op) {
        case 0: A = Wi2;  B = Wc11;              C = w1;               ldc = 512; break;
        case 1: A = Wi2;  B = Wc12;              C = w1 + 256;         ldc = 512; break;
        case 2: A = Wm1b; B = Wc21;              C = w2;               ldc = 512; break;
        case 3: A = Wm1b; B = Wc22;              C = w2 + 256;         ldc = 512; break;
        case 4: A = Wm2b; B = Wfa;               C = w3;               ldc = 256; break;
        default:A = Wm2b; B = Wfa + 256 * 256;   C = w3 + 256 * 256;   ldc = 256; break;
    }
    const int m = idx >> 8;
    const int n = idx & 255;
    const float* a = A + (size_t)m * 256;
    const float* b = B + n;
    float s = 0.f;
#pragma unroll 8
    for (int k = 0; k < 256; k++) s = fmaf(__ldg(&a[k]), __ldg(&b[(size_t)k * 256]), s);
    C[(size_t)m * ldc + n] = s;
}
__global__ void fold_bias3_kernel(const float* __restrict__ bi2,
                                  const float* __restrict__ Wc11, const float* __restrict__ Wc12,
                                  const float* __restrict__ bm1b,
                                  const float* __restrict__ Wc21, const float* __restrict__ Wc22,
                                  const float* __restrict__ bm2b, const float* __restrict__ Wfa,
                                  float* __restrict__ beta1, float* __restrict__ beta2,
                                  float* __restrict__ betaAB) {
    const int op = blockIdx.y;
    const int n = blockIdx.x;
    const int lane = threadIdx.x;
    const float *b, *Wl, *Wr;
    float* out;
    if (op == 0)      { b = bi2;  Wl = Wc11; Wr = Wc12;            out = beta1; }
    else if (op == 1) { b = bm1b; Wl = Wc21; Wr = Wc22;            out = beta2; }
    else              { b = bm2b; Wl = Wfa;  Wr = Wfa + 256 * 256; out = betaAB; }
    const float* W = (n < 256) ? Wl : Wr;
    const int nn = n & 255;
    float s = 0.f;
    for (int k = lane; k < 256; k += 32)
        s = fmaf(__ldg(&b[k]), __ldg(&W[k * 256 + nn]), s);
#pragma unroll
    for (int o = 16; o; o >>= 1) s += __shfl_xor_sync(0xffffffff, s, o);
    if (lane == 0) out[n] = s;
}

// ---------------- pipelined HMMA GEMM, 128x128 tile ----------
constexpr int LDS = 40;
constexpr int TILE_B  = 128 * LDS * 2;
constexpr int STAGE_B = 4 * TILE_B;
constexpr int HM_SMEM = 2 * STAGE_B;

__global__ void __launch_bounds__(256, 2)
hmma_gemm(const float* __restrict__ A, const float* __restrict__ A2, int lda, int splitK,
          const __nv_bfloat16* __restrict__ Bh, const __nv_bfloat16* __restrict__ Bl, int Kpad,
          const float* __restrict__ bias, float* __restrict__ C, int ldc,
          int M, int Kreal, int relu)
{
    extern __shared__ char hsm[];
    const uint32_t sb = smem_u32(hsm);

    const int tid  = threadIdx.x;
    const int wid  = tid >> 5;
    const int lane = tid & 31;
    const int brow = blockIdx.y * 128;
    const int bcol = blockIdx.x * 128;
    const int wm   = (wid & 3) * 32;
    const int wn   = (wid >> 2) * 64;

    float acc[2][8][4];
#pragma unroll
    for (int i = 0; i < 2; i++)
#pragma unroll
        for (int j = 0; j < 8; j++)
#pragma unroll
            for (int q = 0; q < 4; q++) acc[i][j][q] = 0.f;

    const int arow = tid >> 1;
    const int akb  = (tid & 1) * 16;

    const int lg = lane >> 3;
    const int lr = lane & 7;
    const int a_moff = ((lg & 1) ? 8 : 0) + lr;
    const int a_koff = (lg & 2) ? 8 : 0;
    const int b_noff = ((lg & 2) ? 8 : 0) + lr;
    const int b_koff = (lg & 1) ? 8 : 0;

    const int nC = Kpad >> 5;
    float4 av[4];

    auto loadA = [&](int c) {
        const int k0 = c * 32;
        const float* Abase = A; int kb = k0;
        if (A2 && k0 >= splitK) { Abase = A2; kb = k0 - splitK; }
        const int grow = brow + arow;
        const bool rowok = (grow < M);
        const bool fastk = (k0 + 32 <= Kreal);
        const float* src = Abase + (size_t)grow * lda + kb + akb;
#pragma unroll
        for (int i = 0; i < 4; i++) {
            float4 v = make_float4(0.f, 0.f, 0.f, 0.f);
            if (rowok) {
                if (fastk) v = *(const float4*)(src + i * 4);
                else {
                    const int gk = k0 + akb + i * 4;
                    float tmp[4] = {0.f, 0.f, 0.f, 0.f};
                    for (int j = 0; j < 4; j++)
                        if (gk + j < Kreal) tmp[j] = src[i * 4 + j];
                    v = make_float4(tmp[0], tmp[1], tmp[2], tmp[3]);
                }
            }
            av[i] = v;
        }
    };
    auto storeA = [&](uint32_t stg) {
#pragma unroll
        for (int i = 0; i < 4; i++) {
            float4 v = av[i];
            __nv_bfloat16 hx = __float2bfloat16(v.x), hy = __float2bfloat16(v.y);
            __nv_bfloat16 hz = __float2bfloat16(v.z), hw = __float2bfloat16(v.w);
            __nv_bfloat16 lx = __float2bfloat16(v.x - __bfloat162float(hx));
            __nv_bfloat16 ly = __float2bfloat16(v.y - __bfloat162float(hy));
            __nv_bfloat16 lz = __float2bfloat16(v.z - __bfloat162float(hz));
            __nv_bfloat16 lw = __float2bfloat16(v.w - __bfloat162float(hw));
            const uint32_t off = (uint32_t)(arow * LDS + akb + i * 4) * 2;
            asm volatile("st.shared.v2.b32 [%0], {%1,%2};"
                         :: "r"(stg + off), "r"(pack2(hx, hy)), "r"(pack2(hz, hw)));
            asm volatile("st.shared.v2.b32 [%0], {%1,%2};"
                         :: "r"(stg + TILE_B + off), "r"(pack2(lx, ly)), "r"(pack2(lz, lw)));
        }
    };
    auto cpaB = [&](int c, uint32_t stg) {
        const int k0 = c * 32;
        const int nrow = tid >> 1;
        const __nv_bfloat16* sh = Bh + (size_t)(bcol + nrow) * Kpad + k0 + akb;
        const __nv_bfloat16* sl = Bl + (size_t)(bcol + nrow) * Kpad + k0 + akb;
        const uint32_t off0 = (uint32_t)(nrow * LDS + akb) * 2;
#pragma unroll
        for (int j = 0; j < 2; j++) {
            cpa16(stg + 2 * TILE_B + off0 + j * 16, sh + j * 8);
            cpa16(stg + 3 * TILE_B + off0 + j * 16, sl + j * 8);
        }
    };
    auto compute = [&](uint32_t base) {
#pragma unroll
        for (int ks = 0; ks < 2; ks++) {
            const int kk = ks * 16;
            uint32_t ah[2][4], al[2][4];
#pragma unroll
            for (int mt = 0; mt < 2; mt++) {
                const uint32_t aoff =
                    (uint32_t)((wm + mt * 16 + a_moff) * LDS + kk + a_koff) * 2;
                ldmx4(ah[mt], base + aoff);
                ldmx4(al[mt], base + TILE_B + aoff);
            }
#pragma unroll
            for (int p = 0; p < 4; p++) {
                const uint32_t boff =
                    (uint32_t)((wn + p * 16 + b_noff) * LDS + kk + b_koff) * 2;
                uint32_t bhf[4], blf[4];
                ldmx4(bhf, base + 2 * TILE_B + boff);
                ldmx4(blf, base + 3 * TILE_B + boff);
#pragma unroll
                for (int mt = 0; mt < 2; mt++) {
#pragma unroll
                    for (int q = 0; q < 2; q++) {
                        float* c = acc[mt][p * 2 + q];
                        mma16816(c, ah[mt], &bhf[q * 2]);
                        mma16816(c, ah[mt], &blf[q * 2]);
                        mma16816(c, al[mt], &bhf[q * 2]);
                    }
                }
            }
        }
    };

    loadA(0);
    cpaB(0, sb);
    asm volatile("cp.async.commit_group;");
    storeA(sb);
    asm volatile("cp.async.wait_group 0;");
    __syncthreads();

    for (int c = 0; c < nC; c++) {
        const uint32_t cur = sb + (uint32_t)(c & 1) * STAGE_B;
        const uint32_t nxt = sb + (uint32_t)((c + 1) & 1) * STAGE_B;
        const bool more = (c + 1 < nC);
        if (more) {
            loadA(c + 1);
            cpaB(c + 1, nxt);
            asm volatile("cp.async.commit_group;");
        }
        compute(cur);
        if (more) {
            storeA(nxt);
            asm volatile("cp.async.wait_group 0;");
        }
        __syncthreads();
    }

    const int crow0 = brow + wm + (lane >> 2);
    const int ccol0 = bcol + wn + (lane & 3) * 2;
#pragma unroll
    for (int mt = 0; mt < 2; mt++) {
#pragma unroll
        for (int nt = 0; nt < 8; nt++) {
            const int col = ccol0 + nt * 8;
            float bx = 0.f, by = 0.f;
            if (bias) { bx = __ldg(&bias[col]); by = __ldg(&bias[col + 1]); }
            const int r0 = crow0 + mt * 16;
            const int r1 = r0 + 8;
            float v0 = acc[mt][nt][0] + bx, v1 = acc[mt][nt][1] + by;
            float v2 = acc[mt][nt][2] + bx, v3 = acc[mt][nt][3] + by;
            if (relu) {
                v0 = fmaxf(v0, 0.f); v1 = fmaxf(v1, 0.f);
                v2 = fmaxf(v2, 0.f); v3 = fmaxf(v3, 0.f);
            }
            if (r0 < M) *(float2*)(C + (size_t)r0 * ldc + col) = make_float2(v0, v1);
            if (r1 < M) *(float2*)(C + (size_t)r1 * ldc + col) = make_float2(v2, v3);
        }
    }
}

// ---------------- SIMT SGEMM (final classifier) ----------------
__global__ __launch_bounds__(256, 2)
void sgemm_kernel(const float* __restrict__ A, int lda,
                  const float* __restrict__ W, const float* __restrict__ bias,
                  float* __restrict__ C, int ldc,
                  int M, int N, int K, int doRelu)
{
    __shared__ float As[16][128];
    __shared__ float Bs[16][128];
    const int t = threadIdx.x;
    const int brow = blockIdx.y * 128;
    const int bcol = blockIdx.x * 128;
    const int tx = t & 15;
    const int ty = t >> 4;
    const bool nvec = ((N & 3) == 0);

    float acc[8][8];
#pragma unroll
    for (int i = 0; i < 8; i++)
#pragma unroll
        for (int j = 0; j < 8; j++) acc[i][j] = 0.f;

    const int ar  = t >> 1;
    const int akv = (t & 1) * 2;

    for (int k0 = 0; k0 < K; k0 += 16) {
#pragma unroll
        for (int i = 0; i < 2; i++) {
            const int kv = akv + i;
            const int gk = k0 + kv * 4;
            const int grow = brow + ar;
            float4 v = make_float4(0.f, 0.f, 0.f, 0.f);
            if (grow < M && gk + 3 < K)
                v = *(const float4*)(A + (size_t)grow * lda + gk);
            else if (grow < M) {
                float tmp[4] = {0.f, 0.f, 0.f, 0.f};
                for (int j = 0; j < 4; j++) if (gk + j < K) tmp[j] = A[(size_t)grow * lda + gk + j];
                v = make_float4(tmp[0], tmp[1], tmp[2], tmp[3]);
            }
            As[kv * 4 + 0][ar] = v.x; As[kv * 4 + 1][ar] = v.y;
            As[kv * 4 + 2][ar] = v.z; As[kv * 4 + 3][ar] = v.w;
        }
#pragma unroll
        for (int i = 0; i < 2; i++) {
            const int idx = t + i * 256;
            const int wr = idx >> 5;
            const int wc = (idx & 31) * 4;
            float4 v = make_float4(0.f, 0.f, 0.f, 0.f);
            const int gk = k0 + wr;
            const int gc = bcol + wc;
            if (gk < K) {
                if (nvec && gc + 3 < N) v = *(const float4*)(W + (size_t)gk * N + gc);
                else {
                    float tmp[4] = {0.f, 0.f, 0.f, 0.f};
                    for (int j = 0; j < 4; j++) if (gc + j < N) tmp[j] = W[(size_t)gk * N + gc + j];
                    v = make_float4(tmp[0], tmp[1], tmp[2], tmp[3]);
                }
            }
            Bs[wr][wc + 0] = v.x; Bs[wr][wc + 1] = v.y;
            Bs[wr][wc + 2] = v.z; Bs[wr][wc + 3] = v.w;
        }
        __syncthreads();
#pragma unroll
        for (int kk = 0; kk < 16; kk++) {
            float a[8], b[8];
#pragma unroll
            for (int i = 0; i < 8; i++) a[i] = As[kk][ty * 8 + i];
#pragma unroll
            for (int j = 0; j < 8; j++) b[j] = Bs[kk][tx * 8 + j];
#pragma unroll
            for (int i = 0; i < 8; i++)
#pragma unroll
                for (int j = 0; j < 8; j++)
                    acc[i][j] = fmaf(a[i], b[j], acc[i][j]);
        }
        __syncthreads();
    }
#pragma unroll
    for (int i = 0; i < 8; i++) {
        const int grow = brow + ty * 8 + i;
        if (grow >= M) continue;
#pragma unroll
        for (int j = 0; j < 8; j++) {
            const int gc = bcol + tx * 8 + j;
            if (gc >= N) continue;
            float v = acc[i][j];
            if (bias) v += bias[gc];
            if (doRelu) v = fmaxf(v, 0.f);
            C[(size_t)grow * ldc + gc] = v;
        }
    }
}

// ---------------- CSR build (batched) ----------------
__global__ void zero4_i_kernel(int* a, int* b, int* c, int* d, int n) {
    int i = blockIdx.x * blockDim.x + threadIdx.x;
    if (i < n) { a[i] = 0; b[i] = 0; c[i] = 0; d[i] = 0; }
}
__global__ void hist2_kernel(const int* __restrict__ ei1, const int* __restrict__ ei2,
                             int* cnt1, int* cnt2, int E) {
    int e = blockIdx.x * blockDim.x + threadIdx.x;
    if (e < E) atomicAdd(&cnt1[ei1[E + e]], 1);
    else if (e < 2 * E) atomicAdd(&cnt2[ei2[E + (e - E)]], 1);
}
__global__ void scan_partial2(const int* __restrict__ in1, const int* __restrict__ in2,
                              int* __restrict__ out1, int* __restrict__ out2,
                              int* __restrict__ bs1, int* __restrict__ bs2, int n) {
    const int* in = blockIdx.y ? in2 : in1;
    int* outp = blockIdx.y ? out2 : out1;
    int* bs = blockIdx.y ? bs2 : bs1;
    __shared__ int s[256];
    int t = threadIdx.x;
    int idx = blockIdx.x * 256 + t;
    s[t] = (idx < n) ? in[idx] : 0;
    __syncthreads();
#pragma unroll
    for (int d = 1; d < 256; d <<= 1) {
        int add = (t >= d) ? s[t - d] : 0;
        __syncthreads();
        s[t] += add;
        __syncthreads();
    }
    if (idx < n) outp[idx] = s[t];
    if (t == 255) bs[blockIdx.x] = s[255];
}
__global__ void scan_block2(int* __restrict__ bs1, int* __restrict__ bs2, int nb) {
    int* bs = blockIdx.y ? bs2 : bs1;
    __shared__ int s[256];
    int t = threadIdx.x;
    s[t] = (t < nb) ? bs[t] : 0;
    __syncthreads();
#pragma unroll
    for (int d = 1; d < 256; d <<= 1) {
        int add = (t >= d) ? s[t - d] : 0;
        __syncthreads();
        s[t] += add;
        __syncthreads();
    }
    if (t < nb) bs[t] = s[t];
}
__global__ void scan_add2(const int* __restrict__ s1, const int* __restrict__ s2,
                          const int* __restrict__ bs1, const int* __restrict__ bs2,
                          int* __restrict__ row1, int* __restrict__ row2, int n) {
    const int* scanned = blockIdx.y ? s2 : s1;
    const int* bs = blockIdx.y ? bs2 : bs1;
    int* row = blockIdx.y ? row2 : row1;
    int idx = blockIdx.x * blockDim.x + threadIdx.x;
    if (idx < n) {
        int b = idx >> 8;
        row[idx + 1] = scanned[idx] + (b > 0 ? bs[b - 1] : 0);
        if (idx == 0) row[0] = 0;
    }
}
__global__ void fill_csr2(const int* __restrict__ ei1, const int* __restrict__ ei2,
                          const int* __restrict__ row1, const int* __restrict__ row2,
                          int* __restrict__ cur1, int* __restrict__ cur2,
                          int* __restrict__ csr1, int* __restrict__ csr2, int E) {
    int e = blockIdx.x * blockDim.x + threadIdx.x;
    if (e < E) {
        int d = ei1[E + e];
        csr1[row1[d] + atomicAdd(&cur1[d], 1)] = ei1[e];
    } else if (e < 2 * E) {
        int e2 = e - E;
        int d = ei2[E + e2];
        csr2[row2[d] + atomicAdd(&cur2[d], 1)] = ei2[e2];
    }
}
__global__ void dinv2_kernel(const int* __restrict__ cnt1, const int* __restrict__ cnt2,
                             float* dinv1, float* dinv2, int n) {
    int i = blockIdx.x * blockDim.x + threadIdx.x;
    if (i < n) dinv1[i] = rsqrtf((float)cnt1[i] + 1.0f);
    else if (i < 2 * n) dinv2[i - n] = rsqrtf((float)cnt2[i - n] + 1.0f);
}

// ---------------- fused GCN aggregate ----
__global__ __launch_bounds__(256, 8)
void gather_conv_kernel(const int* __restrict__ row, const int* __restrict__ csr,
                        const float* __restrict__ dinv, const float* __restrict__ hw, int ldh,
                        const float* __restrict__ bias, float* __restrict__ out, int N) {
    const int d = blockIdx.x * 8 + (threadIdx.x >> 5);
    const int lane = threadIdx.x & 31;
    if (d >= N) return;
    const float dd = dinv[d];

    const float4* self = (const float4*)(hw + (size_t)d * ldh);
    float4 a0 = __ldg(&self[lane]);
    float4 a1 = __ldg(&self[lane + 32]);
    const float sw = dd * dd;
    a0.x *= sw; a0.y *= sw; a0.z *= sw; a0.w *= sw;
    a1.x *= sw; a1.y *= sw; a1.z *= sw; a1.w *= sw;

    const int start = row[d], end = row[d + 1];
#pragma unroll 2
    for (int e = start; e < end; e++) {
        const int s = __ldg(&csr[e]);
        const float nrm = __ldg(&dinv[s]) * dd;
        const float4* hs = (const float4*)(hw + (size_t)s * ldh);
        float4 v0 = __ldg(&hs[lane]);
        float4 v1 = __ldg(&hs[lane + 32]);
        a0.x = fmaf(v0.x, nrm, a0.x); a0.y = fmaf(v0.y, nrm, a0.y);
        a0.z = fmaf(v0.z, nrm, a0.z); a0.w = fmaf(v0.w, nrm, a0.w);
        a1.x = fmaf(v1.x, nrm, a1.x); a1.y = fmaf(v1.y, nrm, a1.y);
        a1.z = fmaf(v1.z, nrm, a1.z); a1.w = fmaf(v1.w, nrm, a1.w);
    }

    const float4 b0 = __ldg(&((const float4*)bias)[lane]);
    const float4 b1 = __ldg(&((const float4*)bias)[lane + 32]);
    a0.x = fmaxf(a0.x + b0.x, 0.f); a0.y = fmaxf(a0.y + b0.y, 0.f);
    a0.z = fmaxf(a0.z + b0.z, 0.f); a0.w = fmaxf(a0.w + b0.w, 0.f);
    a1.x = fmaxf(a1.x + b1.x, 0.f); a1.y = fmaxf(a1.y + b1.y, 0.f);
    a1.z = fmaxf(a1.z + b1.z, 0.f); a1.w = fmaxf(a1.w + b1.w, 0.f);
    float4* orow = (float4*)(out + (size_t)d * DIM);
    orow[lane] = a0;
    orow[lane + 32] = a1;
}

// ---------------- scatter-mean + fixup + softmax ----------------
__device__ __forceinline__ void red4(float* p, float a, float b, float c, float d) {
    asm volatile("red.global.add.v4.f32 [%0], {%1,%2,%3,%4};"
                 :: "l"(p), "f"(a), "f"(b), "f"(c), "f"(d) : "memory");
}
__global__ void zero_rc_kernel(float* r, float* c1, float* c2, int R, int nb) {
    int i = blockIdx.x * blockDim.x + threadIdx.x;
    if (i < R) r[i] = 0.f;
    if (i < nb) { c1[i] = 0.f; c2[i] = 0.f; }
}
__global__ void smean_scatter_kernel(const int* __restrict__ i1, const int* __restrict__ i2,
                                     const float* __restrict__ h, float* __restrict__ r,
                                     float* __restrict__ c1, float* __restrict__ c2, int T) {
    int w = (blockIdx.x * blockDim.x + threadIdx.x) >> 5;
    int lane = threadIdx.x & 31;
    if (w >= T) return;
    int a = i1[w], b = i2[w];
    const float4* hr = (const float4*)(h + (size_t)w * DIM);
    float* ra = r + (size_t)a * (2 * DIM);
    float* rb = r + (size_t)b * (2 * DIM) + DIM;
#pragma unroll
    for (int i = 0; i < 2; i++) {
        float4 v = hr[lane + i * 32];
        red4(ra + (lane + i * 32) * 4, v.x, v.y, v.z, v.w);
        red4(rb + (lane + i * 32) * 4, v.x, v.y, v.z, v.w);
    }
    if (lane == 0) { atomicAdd(&c1[a], 1.f); atomicAdd(&c2[b], 1.f); }
}
__global__ void smean_div_kernel(float* __restrict__ r, const float* __restrict__ c1,
                                 const float* __restrict__ c2, int total) {
    int idx = blockIdx.x * blockDim.x + threadIdx.x;
    if (idx < total) {
        int row = idx >> 9;
        int col = idx & 511;
        float c = (col < DIM) ? c1[row] : c2[row];
        r[idx] = r[idx] / fmaxf(c, 1.f);
    }
}
__global__ void fixup_relu_kernel(float* __restrict__ t5, const float* __restrict__ c1,
                                  const float* __restrict__ c2,
                                  const float* __restrict__ betaAB, int nb) {
    int idx = blockIdx.x * blockDim.x + threadIdx.x;
    if (idx >= nb * 256) return;
    int i = idx >> 8;
    int n = idx & 255;
    float v = t5[idx];
    if (c1[i] > 0.f) v += betaAB[n];
    if (c2[i] > 0.f) v += betaAB[256 + n];
    t5[idx] = fmaxf(v, 0.f);
}
__global__ void logsoftmax_kernel(const float* __restrict__ logits, float* __restrict__ out, int n) {
    int i = blockIdx.x * blockDim.x + threadIdx.x;
    if (i >= n) return;
    float v[NC];
    float m = -1e30f;
#pragma unroll
    for (int j = 0; j < NC; j++) { v[j] = logits[i * NC + j]; m = fmaxf(m, v[j]); }
    float s = 0.f;
#pragma unroll
    for (int j = 0; j < NC; j++) s += expf(v[j] - m);
    float lse = m + logf(s);
#pragma unroll
    for (int j = 0; j < NC; j++) out[i * NC + j] = v[j] - lse;
}

// ---------------- host launch ----------------
extern "C" void kernel_launch(void* const* d_in, const int* in_sizes, int n_in,
                              void* d_out, int out_size)
{
    const float* x    = (const float*)d_in[0];
    const int*   ei1  = (const int*)d_in[1];
    const int*   ei2  = (const int*)d_in[2];
    const int*   idx1 = (const int*)d_in[3];
    const int*   idx2 = (const int*)d_in[4];
    const float* W_i1 = (const float*)d_in[5];
    const float* b_i1 = (const float*)d_in[6];
    const float* W_i2 = (const float*)d_in[7];
    const float* b_i2 = (const float*)d_in[8];
    const float* Wc11 = (const float*)d_in[9];
    const float* bc11 = (const float*)d_in[10];
    const float* Wc12 = (const float*)d_in[11];
    const float* bc12 = (const float*)d_in[12];
    const float* Wc21 = (const float*)d_in[13];
    const float* bc21 = (const float*)d_in[14];
    const float* Wc22 = (const float*)d_in[15];
    const float* bc22 = (const float*)d_in[16];
    const float* W_m1a = (const float*)d_in[17];
    const float* b_m1a = (const float*)d_in[18];
    const float* W_m1b = (const float*)d_in[19];
    const float* b_m1b = (const float*)d_in[20];
    const float* W_m2a = (const float*)d_in[21];
    const float* b_m2a = (const float*)d_in[22];
    const float* W_m2b = (const float*)d_in[23];
    const float* b_m2b = (const float*)d_in[24];
    const float* W_fa = (const float*)d_in[25];
    const float* b_fa = (const float*)d_in[26];
    const float* W_fb = (const float*)d_in[27];
    const float* b_fb = (const float*)d_in[28];
    float* out = (float*)d_out;

    const int T = T_NODES, E = E_EDGES;

    float *t0, *hw, *h1, *h2, *dinv1, *dinv2, *r, *c1, *c2, *t5, *logits;
    float *wtmp1, *wtmp2, *wtmp3, *beta1, *beta2, *betaAB;
    int *cnt1, *cnt2, *row1, *row2, *csr1, *csr2, *cur1, *cur2, *stmp1, *stmp2, *bsum1, *bsum2;
    __nv_bfloat16* wb;
    cudaGetSymbolAddress((void**)&t0, g_t0);
    cudaGetSymbolAddress((void**)&hw, g_hw);
    cudaGetSymbolAddress((void**)&h1, g_h1);
    cudaGetSymbolAddress((void**)&h2, g_h2);
    cudaGetSymbolAddress((void**)&dinv1, g_dinv1);
    cudaGetSymbolAddress((void**)&dinv2, g_dinv2);
    cudaGetSymbolAddress((void**)&r, g_r);
    cudaGetSymbolAddress((void**)&c1, g_c1);
    cudaGetSymbolAddress((void**)&c2, g_c2);
    cudaGetSymbolAddress((void**)&t5, g_t5);
    cudaGetSymbolAddress((void**)&logits, g_logits);
    cudaGetSymbolAddress((void**)&wb, g_wb);
    cudaGetSymbolAddress((void**)&wtmp1, g_wtmp1);
    cudaGetSymbolAddress((void**)&wtmp2, g_wtmp2);
    cudaGetSymbolAddress((void**)&wtmp3, g_wtmp3);
    cudaGetSymbolAddress((void**)&beta1, g_beta1);
    cudaGetSymbolAddress((void**)&beta2, g_beta2);
    cudaGetSymbolAddress((void**)&betaAB, g_betaAB);
    cudaGetSymbolAddress((void**)&cnt1, g_cnt1);
    cudaGetSymbolAddress((void**)&cnt2, g_cnt2);
    cudaGetSymbolAddress((void**)&row1, g_row1);
    cudaGetSymbolAddress((void**)&row2, g_row2);
    cudaGetSymbolAddress((void**)&csr1, g_csr1);
    cudaGetSymbolAddress((void**)&csr2, g_csr2);
    cudaGetSymbolAddress((void**)&cur1, g_cur1);
    cudaGetSymbolAddress((void**)&cur2, g_cur2);
    cudaGetSymbolAddress((void**)&stmp1, g_stmp1);
    cudaGetSymbolAddress((void**)&stmp2, g_stmp2);
    cudaGetSymbolAddress((void**)&bsum1, g_bsum1);
    cudaGetSymbolAddress((void**)&bsum2, g_bsum2);

    cudaFuncSetAttribute(hmma_gemm, cudaFuncAttributeMaxDynamicSharedMemorySize, HM_SMEM);

    size_t off[NSLOT];
    {
        size_t o = 0;
        for (int i = 0; i < NSLOT; i++) { off[i] = o; o += 2 * (size_t)SLOT_N[i] * SLOT_K[i]; }
    }
    auto sh_ = [&](int s) { return wb + off[s]; };
    auto sl_ = [&](int s) { return wb + off[s] + (size_t)SLOT_N[s] * SLOT_K[s]; };

    const int threads = 256;
    const dim3 gT(2, (T + 127) / 128);
    const dim3 gT512(4, (T + 127) / 128);
    const int blkT = (T + threads - 1) / threads;
    const int blk2E = (2 * E + threads - 1) / threads;
    const int nScanBlk = (T + 255) / 256;
    const int gBlk = (T + 7) / 8;
    const int R = NB * 2 * DIM;

    cudaStream_t s2 = g_aux.s2;

    auto prepS = [&](const float* W, int s, int Nw, int Kreal, cudaStream_t st) {
        int tot = SLOT_N[s] * SLOT_K[s];
        prep_w_kernel<<<(tot + threads - 1) / threads, threads, 0, st>>>(
            W, Nw, SLOT_N[s], Kreal, SLOT_K[s], sh_(s), sl_(s));
    };

    // ================= fork: side stream does folds/preps/CSR under GEMM1 ====
    cudaEventRecord(g_aux.evF, 0);
    cudaStreamWaitEvent(s2, g_aux.evF, 0);

    // --- side stream (s2): weight folds + preps + CSR build + zeroing ---
    fold_all_kernel<<<dim3(256, 6), threads, 0, s2>>>(W_i2, Wc11, Wc12,
                                                      W_m1b, Wc21, Wc22,
                                                      W_m2b, W_fa,
                                                      wtmp1, wtmp2, wtmp3);
    fold_bias3_kernel<<<dim3(512, 3), 32, 0, s2>>>(b_i2, Wc11, Wc12, b_m1b, Wc21, Wc22,
                                                   b_m2b, W_fa, beta1, beta2, betaAB);
    prepS(wtmp1, 1, 512, 256, s2);
    prepS(wtmp2, 2, 512, 256, s2);
    prepS(W_m1a, 3, 256, 512, s2);
    prepS(W_m2a, 4, 256, 512, s2);
    prepS(wtmp3, 5, 256, 512, s2);
    zero4_i_kernel<<<blkT, threads, 0, s2>>>(cnt1, cnt2, cur1, cur2, T);
    hist2_kernel<<<blk2E, threads, 0, s2>>>(ei1, ei2, cnt1, cnt2, E);
    scan_partial2<<<dim3(nScanBlk, 2), 256, 0, s2>>>(cnt1, cnt2, stmp1, stmp2, bsum1, bsum2, T);
    scan_block2<<<dim3(1, 2), 256, 0, s2>>>(bsum1, bsum2, nScanBlk);
    scan_add2<<<dim3(blkT, 2), threads, 0, s2>>>(stmp1, stmp2, bsum1, bsum2, row1, row2, T);
    fill_csr2<<<blk2E, threads, 0, s2>>>(ei1, ei2, row1, row2, cur1, cur2, csr1, csr2, E);
    dinv2_kernel<<<(2 * T + threads - 1) / threads, threads, 0, s2>>>(cnt1, cnt2, dinv1, dinv2, T);
    zero_rc_kernel<<<(R + threads - 1) / threads, threads, 0, s2>>>(r, c1, c2, R, NB);
    cudaEventRecord(g_aux.evJ, s2);

    // --- main stream: prep i1 + GEMM1 (runs concurrently with s2) ---
    prepS(W_i1, 0, 256, F_IN, 0);
    hmma_gemm<<<gT, threads, HM_SMEM>>>(x, nullptr, F_IN, 0, sh_(0), sl_(0), 4672,
                                        b_i1, t0, 256, T, F_IN, 1);

    // ================= join =================
    cudaStreamWaitEvent(0, g_aux.evJ, 0);

    // ---- layer 1 ----
    hmma_gemm<<<gT512, threads, HM_SMEM>>>(t0, nullptr, DIM, 0, sh_(1), sl_(1), 256,
                                           beta1, hw, 512, T, 256, 0);
    gather_conv_kernel<<<gBlk, threads>>>(row1, csr1, dinv1, hw, 512, bc11, h1, T);
    gather_conv_kernel<<<gBlk, threads>>>(row2, csr2, dinv2, hw + 256, 512, bc12, h2, T);
    hmma_gemm<<<gT, threads, HM_SMEM>>>(h1, h2, DIM, 256, sh_(3), sl_(3), 512,
                                        b_m1a, t0, 256, T, 512, 1);

    // ---- layer 2 ----
    hmma_gemm<<<gT512, threads, HM_SMEM>>>(t0, nullptr, DIM, 0, sh_(2), sl_(2), 256,
                                           beta2, hw, 512, T, 256, 0);
    gather_conv_kernel<<<gBlk, threads>>>(row1, csr1, dinv1, hw, 512, bc21, h1, T);
    gather_conv_kernel<<<gBlk, threads>>>(row2, csr2, dinv2, hw + 256, 512, bc22, h2, T);
    hmma_gemm<<<gT, threads, HM_SMEM>>>(h1, h2, DIM, 256, sh_(4), sl_(4), 512,
                                        b_m2a, t0, 256, T, 512, 1);

    // ---- scatter-mean of t0 ----
    smean_scatter_kernel<<<(T + 7) / 8, threads>>>(idx1, idx2, t0, r, c1, c2, T);
    smean_div_kernel<<<(R + threads - 1) / threads, threads>>>(r, c1, c2, R);

    // ---- t5 = relu(r @ Wx + b_fa + indicator-biases) ----
    hmma_gemm<<<dim3(2, (NB + 127) / 128), threads, HM_SMEM>>>(r, nullptr, 2 * DIM, 0,
                                        sh_(5), sl_(5), 512, b_fa, t5, 256, NB, 512, 0);
    fixup_relu_kernel<<<(NB * 256 + threads - 1) / threads, threads>>>(t5, c1, c2, betaAB, NB);

    // ---- classifier + log_softmax ----
    sgemm_kernel<<<dim3(1, (NB + 127) / 128), threads>>>(t5, DIM, W_fb, b_fb, logits, NC, NB, NC, DIM, 0);
    logsoftmax_kernel<<<(NB + threads - 1) / threads, threads>>>(logits, out, NB);
}

// round 17
// speedup vs baseline: 1.8880x; 1.0249x over previous
#include <cuda_runtime.h>
#include <cuda_bf16.h>
#include <math.h>
#include <stdint.h>

// ---------------- problem constants ----------------
constexpr int T_NODES = 50000;
constexpr int NB      = 5000;
constexpr int E_EDGES = 800000;
constexpr int F_IN    = 4652;
constexpr int DIM     = 256;
constexpr int NC      = 5;

// ---------------- aux stream (created at program load, pre-checkpoint) -------
struct AuxStreams {
    cudaStream_t s2 = nullptr;
    cudaEvent_t evF = nullptr, evW = nullptr, evJ = nullptr;
    AuxStreams() {
        cudaStreamCreateWithFlags(&s2, cudaStreamNonBlocking);
        cudaEventCreateWithFlags(&evF, cudaEventDisableTiming);
        cudaEventCreateWithFlags(&evW, cudaEventDisableTiming);
        cudaEventCreateWithFlags(&evJ, cudaEventDisableTiming);
    }
};
static AuxStreams g_aux;

// ---------------- scratch ----------------
__device__ float g_t0 [T_NODES * DIM];
__device__ float g_hw [T_NODES * 2 * DIM];
__device__ float g_h1 [T_NODES * DIM];
__device__ float g_h2 [T_NODES * DIM];
__device__ float g_dinv1[T_NODES];
__device__ float g_dinv2[T_NODES];
__device__ float g_r  [NB * 2 * DIM];
__device__ float g_c1 [NB];
__device__ float g_c2 [NB];
__device__ float g_t5 [NB * DIM];

// CSR scratch
__device__ int g_cnt1[T_NODES];
__device__ int g_cnt2[T_NODES];
__device__ int g_row1[T_NODES + 1];
__device__ int g_row2[T_NODES + 1];
__device__ int g_csr1[E_EDGES];
__device__ int g_csr2[E_EDGES];
__device__ int g_cur1[T_NODES];
__device__ int g_cur2[T_NODES];
__device__ int g_stmp1[T_NODES];
__device__ int g_stmp2[T_NODES];
__device__ int g_bsum1[256];
__device__ int g_bsum2[256];

// weight-fold scratch + folded biases
__device__ __align__(16) float g_wtmp1[256 * 512];
__device__ __align__(16) float g_wtmp2[256 * 512];
__device__ __align__(16) float g_wtmp3[512 * 256];
__device__ __align__(16) float g_beta1[512];
__device__ __align__(16) float g_beta2[512];
__device__ __align__(16) float g_betaAB[512];

// bf16 weight arena: 0=i1, 1=fold1, 2=fold2, 3=m1a, 4=m2a, 5=Wx
constexpr int NSLOT = 6;
constexpr int SLOT_N[NSLOT] = {256, 512, 512, 256, 256, 256};
constexpr int SLOT_K[NSLOT] = {4672, 256, 256, 512, 512, 512};
constexpr int WB_TOTAL = 2 * (256*4672 + 512*256 + 512*256 + 256*512 + 256*512 + 256*512);
__device__ __align__(16) __nv_bfloat16 g_wb[WB_TOTAL];

// ---------------- helpers ----------------
__device__ __forceinline__ uint32_t smem_u32(const void* p) {
    uint32_t a;
    asm("{ .reg .u64 t; cvta.to.shared.u64 t, %1; cvt.u32.u64 %0, t; }" : "=r"(a) : "l"(p));
    return a;
}
__device__ __forceinline__ uint32_t pack2(__nv_bfloat16 a, __nv_bfloat16 b) {
    return (uint32_t)__bfloat16_as_ushort(a) | ((uint32_t)__bfloat16_as_ushort(b) << 16);
}
__device__ __forceinline__ void ldmx4(uint32_t* r, uint32_t addr) {
    asm volatile("ldmatrix.sync.aligned.m8n8.x4.shared.b16 {%0,%1,%2,%3}, [%4];"
                 : "=r"(r[0]), "=r"(r[1]), "=r"(r[2]), "=r"(r[3]) : "r"(addr));
}
__device__ __forceinline__ void mma16816(float* c, const uint32_t* a, const uint32_t* b) {
    asm volatile("mma.sync.aligned.m16n8k16.row.col.f32.bf16.bf16.f32 "
                 "{%0,%1,%2,%3}, {%4,%5,%6,%7}, {%8,%9}, {%0,%1,%2,%3};"
                 : "+f"(c[0]), "+f"(c[1]), "+f"(c[2]), "+f"(c[3])
                 : "r"(a[0]), "r"(a[1]), "r"(a[2]), "r"(a[3]), "r"(b[0]), "r"(b[1]));
}
__device__ __forceinline__ void cpa16(uint32_t dst, const void* src) {
    asm volatile("cp.async.cg.shared.global [%0], [%1], 16;" :: "r"(dst), "l"(src));
}

// ---------------- weight prep ----------------
__global__ void prep_w_kernel(const float* __restrict__ W, int Nw, int Nrows,
                              int Kreal, int Kpad,
                              __nv_bfloat16* __restrict__ bh, __nv_bfloat16* __restrict__ bl) {
    int idx = blockIdx.x * blockDim.x + threadIdx.x;
    if (idx >= Nrows * Kpad) return;
    int n = idx / Kpad, k = idx % Kpad;
    float v = (k < Kreal) ? W[(size_t)k * Nw + n] : 0.f;
    __nv_bfloat16 h = __float2bfloat16(v);
    bh[idx] = h;
    bl[idx] = __float2bfloat16(v - __bfloat162float(h));
}

// ---------------- batched weight folds ----------------
__global__ void fold_all_kernel(const float* __restrict__ Wi2,
                                const float* __restrict__ Wc11, const float* __restrict__ Wc12,
                                const float* __restrict__ Wm1b,
                                const float* __restrict__ Wc21, const float* __restrict__ Wc22,
                                const float* __restrict__ Wm2b, const float* __restrict__ Wfa,
                                float* __restrict__ w1, float* __restrict__ w2,
                                float* __restrict__ w3) {
    const int op = blockIdx.y;
    const int idx = blockIdx.x * blockDim.x + threadIdx.x;
    const float *A, *B;
    float* C;
    int ldc;
    switch (op) {
        case 0: A = Wi2;  B = Wc11;              C = w1;               ldc = 512; break;
        case 1: A = Wi2;  B = Wc12;              C = w1 + 256;         ldc = 512; break;
        case 2: A = Wm1b; B = Wc21;              C = w2;               ldc = 512; break;
        case 3: A = Wm1b; B = Wc22;              C = w2 + 256;         ldc = 512; break;
        case 4: A = Wm2b; B = Wfa;               C = w3;               ldc = 256; break;
        default:A = Wm2b; B = Wfa + 256 * 256;   C = w3 + 256 * 256;   ldc = 256; break;
    }
    const int m = idx >> 8;
    const int n = idx & 255;
    const float* a = A + (size_t)m * 256;
    const float* b = B + n;
    float s = 0.f;
#pragma unroll 8
    for (int k = 0; k < 256; k++) s = fmaf(__ldg(&a[k]), __ldg(&b[(size_t)k * 256]), s);
    C[(size_t)m * ldc + n] = s;
}
__global__ void fold_bias3_kernel(const float* __restrict__ bi2,
                                  const float* __restrict__ Wc11, const float* __restrict__ Wc12,
                                  const float* __restrict__ bm1b,
                                  const float* __restrict__ Wc21, const float* __restrict__ Wc22,
                                  const float* __restrict__ bm2b, const float* __restrict__ Wfa,
                                  float* __restrict__ beta1, float* __restrict__ beta2,
                                  float* __restrict__ betaAB) {
    const int op = blockIdx.y;
    const int n = blockIdx.x;
    const int lane = threadIdx.x;
    const float *b, *Wl, *Wr;
    float* out;
    if (op == 0)      { b = bi2;  Wl = Wc11; Wr = Wc12;            out = beta1; }
    else if (op == 1) { b = bm1b; Wl = Wc21; Wr = Wc22;            out = beta2; }
    else              { b = bm2b; Wl = Wfa;  Wr = Wfa + 256 * 256; out = betaAB; }
    const float* W = (n < 256) ? Wl : Wr;
    const int nn = n & 255;
    float s = 0.f;
    for (int k = lane; k < 256; k += 32)
        s = fmaf(__ldg(&b[k]), __ldg(&W[k * 256 + nn]), s);
#pragma unroll
    for (int o = 16; o; o >>= 1) s += __shfl_xor_sync(0xffffffff, s, o);
    if (lane == 0) out[n] = s;
}

// ---------------- pipelined HMMA GEMM, 128x128 tile ----------
constexpr int LDS = 40;
constexpr int TILE_B  = 128 * LDS * 2;
constexpr int STAGE_B = 4 * TILE_B;
constexpr int HM_SMEM = 2 * STAGE_B;

__global__ void __launch_bounds__(256, 2)
hmma_gemm(const float* __restrict__ A, const float* __restrict__ A2, int lda, int splitK,
          const __nv_bfloat16* __restrict__ Bh, const __nv_bfloat16* __restrict__ Bl, int Kpad,
          const float* __restrict__ bias, float* __restrict__ C, int ldc,
          int M, int Kreal, int relu)
{
    extern __shared__ char hsm[];
    const uint32_t sb = smem_u32(hsm);

    const int tid  = threadIdx.x;
    const int wid  = tid >> 5;
    const int lane = tid & 31;
    const int brow = blockIdx.y * 128;
    const int bcol = blockIdx.x * 128;
    const int wm   = (wid & 3) * 32;
    const int wn   = (wid >> 2) * 64;

    float acc[2][8][4];
#pragma unroll
    for (int i = 0; i < 2; i++)
#pragma unroll
        for (int j = 0; j < 8; j++)
#pragma unroll
            for (int q = 0; q < 4; q++) acc[i][j][q] = 0.f;

    const int arow = tid >> 1;
    const int akb  = (tid & 1) * 16;

    const int lg = lane >> 3;
    const int lr = lane & 7;
    const int a_moff = ((lg & 1) ? 8 : 0) + lr;
    const int a_koff = (lg & 2) ? 8 : 0;
    const int b_noff = ((lg & 2) ? 8 : 0) + lr;
    const int b_koff = (lg & 1) ? 8 : 0;

    const int nC = Kpad >> 5;
    float4 av[4];

    auto loadA = [&](int c) {
        const int k0 = c * 32;
        const float* Abase = A; int kb = k0;
        if (A2 && k0 >= splitK) { Abase = A2; kb = k0 - splitK; }
        const int grow = brow + arow;
        const bool rowok = (grow < M);
        const bool fastk = (k0 + 32 <= Kreal);
        const float* src = Abase + (size_t)grow * lda + kb + akb;
#pragma unroll
        for (int i = 0; i < 4; i++) {
            float4 v = make_float4(0.f, 0.f, 0.f, 0.f);
            if (rowok) {
                if (fastk) v = *(const float4*)(src + i * 4);
                else {
                    const int gk = k0 + akb + i * 4;
                    float tmp[4] = {0.f, 0.f, 0.f, 0.f};
                    for (int j = 0; j < 4; j++)
                        if (gk + j < Kreal) tmp[j] = src[i * 4 + j];
                    v = make_float4(tmp[0], tmp[1], tmp[2], tmp[3]);
                }
            }
            av[i] = v;
        }
    };
    // packed hi/lo conversion: 4 x st.shared.v4 per thread (was 8 x v2)
    auto storeA = [&](uint32_t stg) {
#pragma unroll
        for (int ii = 0; ii < 2; ii++) {
            uint32_t hp[4], lp[4];
#pragma unroll
            for (int i = 0; i < 2; i++) {
                float4 v = av[ii * 2 + i];
                __nv_bfloat16 hx = __float2bfloat16(v.x), hy = __float2bfloat16(v.y);
                __nv_bfloat16 hz = __float2bfloat16(v.z), hw = __float2bfloat16(v.w);
                __nv_bfloat16 lx = __float2bfloat16(v.x - __bfloat162float(hx));
                __nv_bfloat16 ly = __float2bfloat16(v.y - __bfloat162float(hy));
                __nv_bfloat16 lz = __float2bfloat16(v.z - __bfloat162float(hz));
                __nv_bfloat16 lw = __float2bfloat16(v.w - __bfloat162float(hw));
                hp[i * 2 + 0] = pack2(hx, hy);
                hp[i * 2 + 1] = pack2(hz, hw);
                lp[i * 2 + 0] = pack2(lx, ly);
                lp[i * 2 + 1] = pack2(lz, lw);
            }
            const uint32_t off = (uint32_t)(arow * LDS + akb + ii * 8) * 2;   // 16B aligned
            asm volatile("st.shared.v4.b32 [%0], {%1,%2,%3,%4};"
                         :: "r"(stg + off), "r"(hp[0]), "r"(hp[1]), "r"(hp[2]), "r"(hp[3]));
            asm volatile("st.shared.v4.b32 [%0], {%1,%2,%3,%4};"
                         :: "r"(stg + TILE_B + off), "r"(lp[0]), "r"(lp[1]), "r"(lp[2]), "r"(lp[3]));
        }
    };
    auto cpaB = [&](int c, uint32_t stg) {
        const int k0 = c * 32;
        const int nrow = tid >> 1;
        const __nv_bfloat16* sh = Bh + (size_t)(bcol + nrow) * Kpad + k0 + akb;
        const __nv_bfloat16* sl = Bl + (size_t)(bcol + nrow) * Kpad + k0 + akb;
        const uint32_t off0 = (uint32_t)(nrow * LDS + akb) * 2;
#pragma unroll
        for (int j = 0; j < 2; j++) {
            cpa16(stg + 2 * TILE_B + off0 + j * 16, sh + j * 8);
            cpa16(stg + 3 * TILE_B + off0 + j * 16, sl + j * 8);
        }
    };
    auto compute = [&](uint32_t base) {
#pragma unroll
        for (int ks = 0; ks < 2; ks++) {
            const int kk = ks * 16;
            uint32_t ah[2][4], al[2][4];
#pragma unroll
            for (int mt = 0; mt < 2; mt++) {
                const uint32_t aoff =
                    (uint32_t)((wm + mt * 16 + a_moff) * LDS + kk + a_koff) * 2;
                ldmx4(ah[mt], base + aoff);
                ldmx4(al[mt], base + TILE_B + aoff);
            }
#pragma unroll
            for (int p = 0; p < 4; p++) {
                const uint32_t boff =
                    (uint32_t)((wn + p * 16 + b_noff) * LDS + kk + b_koff) * 2;
                uint32_t bhf[4], blf[4];
                ldmx4(bhf, base + 2 * TILE_B + boff);
                ldmx4(blf, base + 3 * TILE_B + boff);
#pragma unroll
                for (int mt = 0; mt < 2; mt++) {
#pragma unroll
                    for (int q = 0; q < 2; q++) {
                        float* c = acc[mt][p * 2 + q];
                        mma16816(c, ah[mt], &bhf[q * 2]);
                        mma16816(c, ah[mt], &blf[q * 2]);
                        mma16816(c, al[mt], &bhf[q * 2]);
                    }
                }
            }
        }
    };

    loadA(0);
    cpaB(0, sb);
    asm volatile("cp.async.commit_group;");
    storeA(sb);
    asm volatile("cp.async.wait_group 0;");
    __syncthreads();

    for (int c = 0; c < nC; c++) {
        const uint32_t cur = sb + (uint32_t)(c & 1) * STAGE_B;
        const uint32_t nxt = sb + (uint32_t)((c + 1) & 1) * STAGE_B;
        const bool more = (c + 1 < nC);
        if (more) {
            loadA(c + 1);
            cpaB(c + 1, nxt);
            asm volatile("cp.async.commit_group;");
        }
        compute(cur);
        if (more) {
            storeA(nxt);
            asm volatile("cp.async.wait_group 0;");
        }
        __syncthreads();
    }

    const int crow0 = brow + wm + (lane >> 2);
    const int ccol0 = bcol + wn + (lane & 3) * 2;
#pragma unroll
    for (int mt = 0; mt < 2; mt++) {
#pragma unroll
        for (int nt = 0; nt < 8; nt++) {
            const int col = ccol0 + nt * 8;
            float bx = 0.f, by = 0.f;
            if (bias) { bx = __ldg(&bias[col]); by = __ldg(&bias[col + 1]); }
            const int r0 = crow0 + mt * 16;
            const int r1 = r0 + 8;
            float v0 = acc[mt][nt][0] + bx, v1 = acc[mt][nt][1] + by;
            float v2 = acc[mt][nt][2] + bx, v3 = acc[mt][nt][3] + by;
            if (relu) {
                v0 = fmaxf(v0, 0.f); v1 = fmaxf(v1, 0.f);
                v2 = fmaxf(v2, 0.f); v3 = fmaxf(v3, 0.f);
            }
            if (r0 < M) *(float2*)(C + (size_t)r0 * ldc + col) = make_float2(v0, v1);
            if (r1 < M) *(float2*)(C + (size_t)r1 * ldc + col) = make_float2(v2, v3);
        }
    }
}

// ---------------- CSR build (batched) ----------------
__global__ void zero4_i_kernel(int* a, int* b, int* c, int* d, int n) {
    int i = blockIdx.x * blockDim.x + threadIdx.x;
    if (i < n) { a[i] = 0; b[i] = 0; c[i] = 0; d[i] = 0; }
}
__global__ void hist2_kernel(const int* __restrict__ ei1, const int* __restrict__ ei2,
                             int* cnt1, int* cnt2, int E) {
    int e = blockIdx.x * blockDim.x + threadIdx.x;
    if (e < E) atomicAdd(&cnt1[ei1[E + e]], 1);
    else if (e < 2 * E) atomicAdd(&cnt2[ei2[E + (e - E)]], 1);
}
__global__ void scan_partial2(const int* __restrict__ in1, const int* __restrict__ in2,
                              int* __restrict__ out1, int* __restrict__ out2,
                              int* __restrict__ bs1, int* __restrict__ bs2, int n) {
    const int* in = blockIdx.y ? in2 : in1;
    int* outp = blockIdx.y ? out2 : out1;
    int* bs = blockIdx.y ? bs2 : bs1;
    __shared__ int s[256];
    int t = threadIdx.x;
    int idx = blockIdx.x * 256 + t;
    s[t] = (idx < n) ? in[idx] : 0;
    __syncthreads();
#pragma unroll
    for (int d = 1; d < 256; d <<= 1) {
        int add = (t >= d) ? s[t - d] : 0;
        __syncthreads();
        s[t] += add;
        __syncthreads();
    }
    if (idx < n) outp[idx] = s[t];
    if (t == 255) bs[blockIdx.x] = s[255];
}
__global__ void scan_block2(int* __restrict__ bs1, int* __restrict__ bs2, int nb) {
    int* bs = blockIdx.y ? bs2 : bs1;
    __shared__ int s[256];
    int t = threadIdx.x;
    s[t] = (t < nb) ? bs[t] : 0;
    __syncthreads();
#pragma unroll
    for (int d = 1; d < 256; d <<= 1) {
        int add = (t >= d) ? s[t - d] : 0;
        __syncthreads();
        s[t] += add;
        __syncthreads();
    }
    if (t < nb) bs[t] = s[t];
}
__global__ void scan_add2(const int* __restrict__ s1, const int* __restrict__ s2,
                          const int* __restrict__ bs1, const int* __restrict__ bs2,
                          int* __restrict__ row1, int* __restrict__ row2, int n) {
    const int* scanned = blockIdx.y ? s2 : s1;
    const int* bs = blockIdx.y ? bs2 : bs1;
    int* row = blockIdx.y ? row2 : row1;
    int idx = blockIdx.x * blockDim.x + threadIdx.x;
    if (idx < n) {
        int b = idx >> 8;
        row[idx + 1] = scanned[idx] + (b > 0 ? bs[b - 1] : 0);
        if (idx == 0) row[0] = 0;
    }
}
__global__ void fill_csr2(const int* __restrict__ ei1, const int* __restrict__ ei2,
                          const int* __restrict__ row1, const int* __restrict__ row2,
                          int* __restrict__ cur1, int* __restrict__ cur2,
                          int* __restrict__ csr1, int* __restrict__ csr2, int E) {
    int e = blockIdx.x * blockDim.x + threadIdx.x;
    if (e < E) {
        int d = ei1[E + e];
        csr1[row1[d] + atomicAdd(&cur1[d], 1)] = ei1[e];
    } else if (e < 2 * E) {
        int e2 = e - E;
        int d = ei2[E + e2];
        csr2[row2[d] + atomicAdd(&cur2[d], 1)] = ei2[e2];
    }
}
__global__ void dinv2_kernel(const int* __restrict__ cnt1, const int* __restrict__ cnt2,
                             float* dinv1, float* dinv2, int n) {
    int i = blockIdx.x * blockDim.x + threadIdx.x;
    if (i < n) dinv1[i] = rsqrtf((float)cnt1[i] + 1.0f);
    else if (i < 2 * n) dinv2[i - n] = rsqrtf((float)cnt2[i - n] + 1.0f);
}

// ---------------- fused GCN aggregate ----
__global__ __launch_bounds__(256, 8)
void gather_conv_kernel(const int* __restrict__ row, const int* __restrict__ csr,
                        const float* __restrict__ dinv, const float* __restrict__ hw, int ldh,
                        const float* __restrict__ bias, float* __restrict__ out, int N) {
    const int d = blockIdx.x * 8 + (threadIdx.x >> 5);
    const int lane = threadIdx.x & 31;
    if (d >= N) return;
    const float dd = dinv[d];

    const float4* self = (const float4*)(hw + (size_t)d * ldh);
    float4 a0 = __ldg(&self[lane]);
    float4 a1 = __ldg(&self[lane + 32]);
    const float sw = dd * dd;
    a0.x *= sw; a0.y *= sw; a0.z *= sw; a0.w *= sw;
    a1.x *= sw; a1.y *= sw; a1.z *= sw; a1.w *= sw;

    const int start = row[d], end = row[d + 1];
#pragma unroll 2
    for (int e = start; e < end; e++) {
        const int s = __ldg(&csr[e]);
        const float nrm = __ldg(&dinv[s]) * dd;
        const float4* hs = (const float4*)(hw + (size_t)s * ldh);
        float4 v0 = __ldg(&hs[lane]);
        float4 v1 = __ldg(&hs[lane + 32]);
        a0.x = fmaf(v0.x, nrm, a0.x); a0.y = fmaf(v0.y, nrm, a0.y);
        a0.z = fmaf(v0.z, nrm, a0.z); a0.w = fmaf(v0.w, nrm, a0.w);
        a1.x = fmaf(v1.x, nrm, a1.x); a1.y = fmaf(v1.y, nrm, a1.y);
        a1.z = fmaf(v1.z, nrm, a1.z); a1.w = fmaf(v1.w, nrm, a1.w);
    }

    const float4 b0 = __ldg(&((const float4*)bias)[lane]);
    const float4 b1 = __ldg(&((const float4*)bias)[lane + 32]);
    a0.x = fmaxf(a0.x + b0.x, 0.f); a0.y = fmaxf(a0.y + b0.y, 0.f);
    a0.z = fmaxf(a0.z + b0.z, 0.f); a0.w = fmaxf(a0.w + b0.w, 0.f);
    a1.x = fmaxf(a1.x + b1.x, 0.f); a1.y = fmaxf(a1.y + b1.y, 0.f);
    a1.z = fmaxf(a1.z + b1.z, 0.f); a1.w = fmaxf(a1.w + b1.w, 0.f);
    float4* orow = (float4*)(out + (size_t)d * DIM);
    orow[lane] = a0;
    orow[lane + 32] = a1;
}

// ---------------- scatter-mean + fused head ----------------
__device__ __forceinline__ void red4(float* p, float a, float b, float c, float d) {
    asm volatile("red.global.add.v4.f32 [%0], {%1,%2,%3,%4};"
                 :: "l"(p), "f"(a), "f"(b), "f"(c), "f"(d) : "memory");
}
__global__ void zero_rc_kernel(float* r, float* c1, float* c2, int R, int nb) {
    int i = blockIdx.x * blockDim.x + threadIdx.x;
    if (i < R) r[i] = 0.f;
    if (i < nb) { c1[i] = 0.f; c2[i] = 0.f; }
}
__global__ void smean_scatter_kernel(const int* __restrict__ i1, const int* __restrict__ i2,
                                     const float* __restrict__ h, float* __restrict__ r,
                                     float* __restrict__ c1, float* __restrict__ c2, int T) {
    int w = (blockIdx.x * blockDim.x + threadIdx.x) >> 5;
    int lane = threadIdx.x & 31;
    if (w >= T) return;
    int a = i1[w], b = i2[w];
    const float4* hr = (const float4*)(h + (size_t)w * DIM);
    float* ra = r + (size_t)a * (2 * DIM);
    float* rb = r + (size_t)b * (2 * DIM) + DIM;
#pragma unroll
    for (int i = 0; i < 2; i++) {
        float4 v = hr[lane + i * 32];
        red4(ra + (lane + i * 32) * 4, v.x, v.y, v.z, v.w);
        red4(rb + (lane + i * 32) * 4, v.x, v.y, v.z, v.w);
    }
    if (lane == 0) { atomicAdd(&c1[a], 1.f); atomicAdd(&c2[b], 1.f); }
}
__global__ void smean_div_kernel(float* __restrict__ r, const float* __restrict__ c1,
                                 const float* __restrict__ c2, int total) {
    int idx = blockIdx.x * blockDim.x + threadIdx.x;
    if (idx < total) {
        int row = idx >> 9;
        int col = idx & 511;
        float c = (col < DIM) ? c1[row] : c2[row];
        r[idx] = r[idx] / fmaxf(c, 1.f);
    }
}
// fused: indicator-bias fixup + relu + classifier GEMV + log_softmax
__global__ __launch_bounds__(256, 8)
void final_head_kernel(const float* __restrict__ t5pre,
                       const float* __restrict__ c1, const float* __restrict__ c2,
                       const float* __restrict__ betaAB,
                       const float* __restrict__ Wfb, const float* __restrict__ bfb,
                       float* __restrict__ out, int nb) {
    const int row = blockIdx.x * 8 + (threadIdx.x >> 5);
    const int lane = threadIdx.x & 31;
    if (row >= nb) return;
    const bool f1 = (c1[row] > 0.f);
    const bool f2 = (c2[row] > 0.f);
    float acc[NC] = {0.f, 0.f, 0.f, 0.f, 0.f};
    const float* trow = t5pre + (size_t)row * DIM;
    for (int k = lane; k < DIM; k += 32) {
        float v = trow[k];
        if (f1) v += __ldg(&betaAB[k]);
        if (f2) v += __ldg(&betaAB[256 + k]);
        v = fmaxf(v, 0.f);
#pragma unroll
        for (int j = 0; j < NC; j++) acc[j] = fmaf(v, __ldg(&Wfb[k * NC + j]), acc[j]);
    }
#pragma unroll
    for (int o = 16; o; o >>= 1)
#pragma unroll
        for (int j = 0; j < NC; j++) acc[j] += __shfl_xor_sync(0xffffffff, acc[j], o);
    if (lane == 0) {
        float v[NC];
        float m = -1e30f;
#pragma unroll
        for (int j = 0; j < NC; j++) { v[j] = acc[j] + bfb[j]; m = fmaxf(m, v[j]); }
        float s = 0.f;
#pragma unroll
        for (int j = 0; j < NC; j++) s += expf(v[j] - m);
        float lse = m + logf(s);
#pragma unroll
        for (int j = 0; j < NC; j++) out[row * NC + j] = v[j] - lse;
    }
}

// ---------------- host launch ----------------
extern "C" void kernel_launch(void* const* d_in, const int* in_sizes, int n_in,
                              void* d_out, int out_size)
{
    const float* x    = (const float*)d_in[0];
    const int*   ei1  = (const int*)d_in[1];
    const int*   ei2  = (const int*)d_in[2];
    const int*   idx1 = (const int*)d_in[3];
    const int*   idx2 = (const int*)d_in[4];
    const float* W_i1 = (const float*)d_in[5];
    const float* b_i1 = (const float*)d_in[6];
    const float* W_i2 = (const float*)d_in[7];
    const float* b_i2 = (const float*)d_in[8];
    const float* Wc11 = (const float*)d_in[9];
    const float* bc11 = (const float*)d_in[10];
    const float* Wc12 = (const float*)d_in[11];
    const float* bc12 = (const float*)d_in[12];
    const float* Wc21 = (const float*)d_in[13];
    const float* bc21 = (const float*)d_in[14];
    const float* Wc22 = (const float*)d_in[15];
    const float* bc22 = (const float*)d_in[16];
    const float* W_m1a = (const float*)d_in[17];
    const float* b_m1a = (const float*)d_in[18];
    const float* W_m1b = (const float*)d_in[19];
    const float* b_m1b = (const float*)d_in[20];
    const float* W_m2a = (const float*)d_in[21];
    const float* b_m2a = (const float*)d_in[22];
    const float* W_m2b = (const float*)d_in[23];
    const float* b_m2b = (const float*)d_in[24];
    const float* W_fa = (const float*)d_in[25];
    const float* b_fa = (const float*)d_in[26];
    const float* W_fb = (const float*)d_in[27];
    const float* b_fb = (const float*)d_in[28];
    float* out = (float*)d_out;

    const int T = T_NODES, E = E_EDGES;

    float *t0, *hw, *h1, *h2, *dinv1, *dinv2, *r, *c1, *c2, *t5;
    float *wtmp1, *wtmp2, *wtmp3, *beta1, *beta2, *betaAB;
    int *cnt1, *cnt2, *row1, *row2, *csr1, *csr2, *cur1, *cur2, *stmp1, *stmp2, *bsum1, *bsum2;
    __nv_bfloat16* wb;
    cudaGetSymbolAddress((void**)&t0, g_t0);
    cudaGetSymbolAddress((void**)&hw, g_hw);
    cudaGetSymbolAddress((void**)&h1, g_h1);
    cudaGetSymbolAddress((void**)&h2, g_h2);
    cudaGetSymbolAddress((void**)&dinv1, g_dinv1);
    cudaGetSymbolAddress((void**)&dinv2, g_dinv2);
    cudaGetSymbolAddress((void**)&r, g_r);
    cudaGetSymbolAddress((void**)&c1, g_c1);
    cudaGetSymbolAddress((void**)&c2, g_c2);
    cudaGetSymbolAddress((void**)&t5, g_t5);
    cudaGetSymbolAddress((void**)&wb, g_wb);
    cudaGetSymbolAddress((void**)&wtmp1, g_wtmp1);
    cudaGetSymbolAddress((void**)&wtmp2, g_wtmp2);
    cudaGetSymbolAddress((void**)&wtmp3, g_wtmp3);
    cudaGetSymbolAddress((void**)&beta1, g_beta1);
    cudaGetSymbolAddress((void**)&beta2, g_beta2);
    cudaGetSymbolAddress((void**)&betaAB, g_betaAB);
    cudaGetSymbolAddress((void**)&cnt1, g_cnt1);
    cudaGetSymbolAddress((void**)&cnt2, g_cnt2);
    cudaGetSymbolAddress((void**)&row1, g_row1);
    cudaGetSymbolAddress((void**)&row2, g_row2);
    cudaGetSymbolAddress((void**)&csr1, g_csr1);
    cudaGetSymbolAddress((void**)&csr2, g_csr2);
    cudaGetSymbolAddress((void**)&cur1, g_cur1);
    cudaGetSymbolAddress((void**)&cur2, g_cur2);
    cudaGetSymbolAddress((void**)&stmp1, g_stmp1);
    cudaGetSymbolAddress((void**)&stmp2, g_stmp2);
    cudaGetSymbolAddress((void**)&bsum1, g_bsum1);
    cudaGetSymbolAddress((void**)&bsum2, g_bsum2);

    cudaFuncSetAttribute(hmma_gemm, cudaFuncAttributeMaxDynamicSharedMemorySize, HM_SMEM);

    size_t off[NSLOT];
    {
        size_t o = 0;
        for (int i = 0; i < NSLOT; i++) { off[i] = o; o += 2 * (size_t)SLOT_N[i] * SLOT_K[i]; }
    }
    auto sh_ = [&](int s) { return wb + off[s]; };
    auto sl_ = [&](int s) { return wb + off[s] + (size_t)SLOT_N[s] * SLOT_K[s]; };

    const int threads = 256;
    const dim3 gT(2, (T + 127) / 128);
    const dim3 gT512(4, (T + 127) / 128);
    const int blkT = (T + threads - 1) / threads;
    const int blk2E = (2 * E + threads - 1) / threads;
    const int nScanBlk = (T + 255) / 256;
    const int gBlk = (T + 7) / 8;
    const int R = NB * 2 * DIM;

    cudaStream_t s2 = g_aux.s2;

    auto prepS = [&](const float* W, int s, int Nw, int Kreal, cudaStream_t st) {
        int tot = SLOT_N[s] * SLOT_K[s];
        prep_w_kernel<<<(tot + threads - 1) / threads, threads, 0, st>>>(
            W, Nw, SLOT_N[s], Kreal, SLOT_K[s], sh_(s), sl_(s));
    };

    // ================= fork =================
    cudaEventRecord(g_aux.evF, 0);
    cudaStreamWaitEvent(s2, g_aux.evF, 0);

    // --- side stream (s2): weights first (evW), then CSR (evJ) ---
    fold_all_kernel<<<dim3(256, 6), threads, 0, s2>>>(W_i2, Wc11, Wc12,
                                                      W_m1b, Wc21, Wc22,
                                                      W_m2b, W_fa,
                                                      wtmp1, wtmp2, wtmp3);
    fold_bias3_kernel<<<dim3(512, 3), 32, 0, s2>>>(b_i2, Wc11, Wc12, b_m1b, Wc21, Wc22,
                                                   b_m2b, W_fa, beta1, beta2, betaAB);
    prepS(wtmp1, 1, 512, 256, s2);
    prepS(wtmp2, 2, 512, 256, s2);
    prepS(W_m1a, 3, 256, 512, s2);
    prepS(W_m2a, 4, 256, 512, s2);
    prepS(wtmp3, 5, 256, 512, s2);
    cudaEventRecord(g_aux.evW, s2);            // weights ready

    zero4_i_kernel<<<blkT, threads, 0, s2>>>(cnt1, cnt2, cur1, cur2, T);
    hist2_kernel<<<blk2E, threads, 0, s2>>>(ei1, ei2, cnt1, cnt2, E);
    scan_partial2<<<dim3(nScanBlk, 2), 256, 0, s2>>>(cnt1, cnt2, stmp1, stmp2, bsum1, bsum2, T);
    scan_block2<<<dim3(1, 2), 256, 0, s2>>>(bsum1, bsum2, nScanBlk);
    scan_add2<<<dim3(blkT, 2), threads, 0, s2>>>(stmp1, stmp2, bsum1, bsum2, row1, row2, T);
    fill_csr2<<<blk2E, threads, 0, s2>>>(ei1, ei2, row1, row2, cur1, cur2, csr1, csr2, E);
    dinv2_kernel<<<(2 * T + threads - 1) / threads, threads, 0, s2>>>(cnt1, cnt2, dinv1, dinv2, T);
    zero_rc_kernel<<<(R + threads - 1) / threads, threads, 0, s2>>>(r, c1, c2, R, NB);
    cudaEventRecord(g_aux.evJ, s2);            // graph structures ready

    // --- main stream: prep i1 + GEMM1 (concurrent with s2) ---
    prepS(W_i1, 0, 256, F_IN, 0);
    hmma_gemm<<<gT, threads, HM_SMEM>>>(x, nullptr, F_IN, 0, sh_(0), sl_(0), 4672,
                                        b_i1, t0, 256, T, F_IN, 1);

    // ---- layer 1: transform needs only weights ----
    cudaStreamWaitEvent(0, g_aux.evW, 0);
    hmma_gemm<<<gT512, threads, HM_SMEM>>>(t0, nullptr, DIM, 0, sh_(1), sl_(1), 256,
                                           beta1, hw, 512, T, 256, 0);
    cudaStreamWaitEvent(0, g_aux.evJ, 0);      // gathers need CSR
    gather_conv_kernel<<<gBlk, threads>>>(row1, csr1, dinv1, hw, 512, bc11, h1, T);
    gather_conv_kernel<<<gBlk, threads>>>(row2, csr2, dinv2, hw + 256, 512, bc12, h2, T);
    hmma_gemm<<<gT, threads, HM_SMEM>>>(h1, h2, DIM, 256, sh_(3), sl_(3), 512,
                                        b_m1a, t0, 256, T, 512, 1);

    // ---- layer 2 ----
    hmma_gemm<<<gT512, threads, HM_SMEM>>>(t0, nullptr, DIM, 0, sh_(2), sl_(2), 256,
                                           beta2, hw, 512, T, 256, 0);
    gather_conv_kernel<<<gBlk, threads>>>(row1, csr1, dinv1, hw, 512, bc21, h1, T);
    gather_conv_kernel<<<gBlk, threads>>>(row2, csr2, dinv2, hw + 256, 512, bc22, h2, T);
    hmma_gemm<<<gT, threads, HM_SMEM>>>(h1, h2, DIM, 256, sh_(4), sl_(4), 512,
                                        b_m2a, t0, 256, T, 512, 1);

    // ---- scatter-mean of t0 ----
    smean_scatter_kernel<<<(T + 7) / 8, threads>>>(idx1, idx2, t0, r, c1, c2, T);
    smean_div_kernel<<<(R + threads - 1) / threads, threads>>>(r, c1, c2, R);

    // ---- t5pre = r @ Wx + b_fa ----
    hmma_gemm<<<dim3(2, (NB + 127) / 128), threads, HM_SMEM>>>(r, nullptr, 2 * DIM, 0,
                                        sh_(5), sl_(5), 512, b_fa, t5, 256, NB, 512, 0);

    // ---- fused head: fixup + relu + classifier + log_softmax ----
    final_head_kernel<<<(NB + 7) / 8, threads>>>(t5, c1, c2, betaAB, W_fb, b_fb, out, NB);
}